// round 2
// baseline (speedup 1.0000x reference)
#include <cuda_runtime.h>
#include <cstdint>
#include <math.h>

#define BB   64
#define HH   2048
#define HIN  66
#define KPAD 128
#define TT   25
#define OUTD 66
#define G4   8192   // 4*H gate rows

// ---------------- device scratch (static globals; no allocation) ----------------
__device__ __align__(256) float g_Wih0p[G4 * KPAD];   // W_ih0 padded 66 -> 128, tf32-rounded
__device__ __align__(256) float g_x[BB * KPAD];       // current input, padded, tf32-rounded
__device__ __align__(256) float g_bias0[G4];
__device__ __align__(256) float g_bias1[G4];
__device__ __align__(256) float g_h0a[BB * HH], g_h0b[BB * HH];
__device__ __align__(256) float g_h1a[BB * HH], g_h1b[BB * HH];
__device__ __align__(256) float g_c0[BB * HH], g_c1[BB * HH];

__device__ __forceinline__ float tf32r(float v) {
    uint32_t u;
    asm("cvt.rna.tf32.f32 %0, %1;" : "=r"(u) : "f"(v));
    return __uint_as_float(u);
}

// ---------------- setup: pack/pad Wih0, fuse biases, init x/h/c ----------------
__global__ void setup_kernel(const float* __restrict__ inputs,
                             const float* __restrict__ hiddens,
                             const float* __restrict__ cells,
                             const float* __restrict__ W_ih0,
                             const float* __restrict__ b_ih0,
                             const float* __restrict__ b_hh0,
                             const float* __restrict__ b_ih1,
                             const float* __restrict__ b_hh1) {
    int i = blockIdx.x * blockDim.x + threadIdx.x;
    const int NW = G4 * KPAD;           // 1048576
    if (i < NW) {
        int r = i >> 7, c = i & 127;
        g_Wih0p[i] = (c < HIN) ? tf32r(W_ih0[r * HIN + c]) : 0.f;
        return;
    }
    i -= NW;
    if (i < BB * KPAD) {
        int c = i & 127, b = i >> 7;
        g_x[i] = (c < HIN) ? tf32r(inputs[b * HIN + c]) : 0.f;
        return;
    }
    i -= BB * KPAD;
    if (i < G4) { g_bias0[i] = b_ih0[i] + b_hh0[i]; return; }
    i -= G4;
    if (i < G4) { g_bias1[i] = b_ih1[i] + b_hh1[i]; return; }
    i -= G4;
    const int NS = BB * HH;             // 131072
    if (i < NS) { g_h0a[i] = tf32r(hiddens[i]); return; }
    i -= NS;
    if (i < NS) { g_h1a[i] = tf32r(hiddens[NS + i]); return; }
    i -= NS;
    if (i < NS) { g_c0[i] = cells[i]; return; }
    i -= NS;
    if (i < NS) { g_c1[i] = cells[NS + i]; return; }
}

// ---------------- GEMM segment: acc += A[64,K] * W[rows,K]^T on a 64x64 tile ----
// Block bn owns weight rows {gsec*H + bn*16 + r : gsec in 0..3, r in 0..15}.
template<int K>
__device__ __forceinline__ void gemm_seg(const float* __restrict__ A,
                                         const float* __restrict__ W,
                                         int bn, int tid, int wm, int wn, int g, int tg,
                                         float (&acc)[4][4],
                                         float (*As)[68], float (*Ws)[68]) {
    for (int k0 = 0; k0 < K; k0 += 64) {
        // stage A tile: 64 rows x 64 k (float4 per thread x4)
        #pragma unroll
        for (int it = 0; it < 4; it++) {
            int s = tid + it * 256;
            int r = s >> 4, c4 = s & 15;
            float4 v = *reinterpret_cast<const float4*>(A + (size_t)r * K + k0 + c4 * 4);
            *reinterpret_cast<float4*>(&As[r][c4 * 4]) = v;
        }
        // stage W tile: 64 gate-rows x 64 k
        #pragma unroll
        for (int it = 0; it < 4; it++) {
            int s = tid + it * 256;
            int jj = s >> 4, c4 = s & 15;
            int wrow = (jj >> 4) * HH + bn * 16 + (jj & 15);
            float4 v = *reinterpret_cast<const float4*>(W + (size_t)wrow * K + k0 + c4 * 4);
            *reinterpret_cast<float4*>(&Ws[jj][c4 * 4]) = v;
        }
        __syncthreads();
        #pragma unroll
        for (int kk = 0; kk < 64; kk += 8) {
            uint32_t a0 = __float_as_uint(As[wm * 16 + g][kk + tg]);
            uint32_t a1 = __float_as_uint(As[wm * 16 + g + 8][kk + tg]);
            uint32_t a2 = __float_as_uint(As[wm * 16 + g][kk + tg + 4]);
            uint32_t a3 = __float_as_uint(As[wm * 16 + g + 8][kk + tg + 4]);
            #pragma unroll
            for (int nt = 0; nt < 4; nt++) {
                int col = wn * 32 + nt * 8 + g;
                uint32_t b0 = __float_as_uint(Ws[col][kk + tg]);
                uint32_t b1 = __float_as_uint(Ws[col][kk + tg + 4]);
                asm volatile(
                    "mma.sync.aligned.m16n8k8.row.col.f32.tf32.tf32.f32 "
                    "{%0,%1,%2,%3}, {%4,%5,%6,%7}, {%8,%9}, {%0,%1,%2,%3};\n"
                    : "+f"(acc[nt][0]), "+f"(acc[nt][1]),
                      "+f"(acc[nt][2]), "+f"(acc[nt][3])
                    : "r"(a0), "r"(a1), "r"(a2), "r"(a3), "r"(b0), "r"(b1));
            }
        }
        __syncthreads();
    }
}

// ---------------- fused LSTM cell: gates GEMM + nonlinearity + state update ----
// grid = 128 blocks (H/16 column tiles), 256 threads (8 warps: 4 M-tiles x 2 N-tiles)
template<int KI>
__global__ void __launch_bounds__(256, 1)
lstm_cell_kernel(const float* __restrict__ actI,   // [BB, KI]
                 const float* __restrict__ Wih,    // [G4, KI]
                 const float* __restrict__ actH,   // [BB, HH]
                 const float* __restrict__ Whh,    // [G4, HH]
                 const float* __restrict__ bias,   // [G4]
                 float* __restrict__ c_state,      // in-place (per-element)
                 float* __restrict__ h_out) {
    __shared__ float As[64][68];
    __shared__ float Ws[64][68];
    const int tid  = threadIdx.x;
    const int lane = tid & 31;
    const int warp = tid >> 5;
    const int g  = lane >> 2, tg = lane & 3;
    const int wm = warp & 3,  wn = warp >> 2;
    const int bn = blockIdx.x;

    float acc[4][4];
    #pragma unroll
    for (int a = 0; a < 4; a++)
        #pragma unroll
        for (int b = 0; b < 4; b++) acc[a][b] = 0.f;

    gemm_seg<KI>(actI, Wih, bn, tid, wm, wn, g, tg, acc, As, Ws);
    gemm_seg<HH>(actH, Whh, bn, tid, wm, wn, g, tg, acc, As, Ws);

    // scatter C fragments to shared (reuse As storage, stride 68)
    float* Gs = &As[0][0];
    {
        int row = wm * 16 + g;
        #pragma unroll
        for (int nt = 0; nt < 4; nt++) {
            int col = wn * 32 + nt * 8 + tg * 2;
            Gs[row * 68 + col]           = acc[nt][0];
            Gs[row * 68 + col + 1]       = acc[nt][1];
            Gs[(row + 8) * 68 + col]     = acc[nt][2];
            Gs[(row + 8) * 68 + col + 1] = acc[nt][3];
        }
    }
    __syncthreads();

    // elementwise LSTM: gates ordered i,f,g,o along jj = gsec*16 + c
    #pragma unroll
    for (int it = 0; it < 4; it++) {
        int s = tid + it * 256;
        int b = s >> 4, c = s & 15;
        int hcol = bn * 16 + c;
        float vi = Gs[b * 68 + c]      + bias[hcol];
        float vf = Gs[b * 68 + 16 + c] + bias[HH + hcol];
        float vg = Gs[b * 68 + 32 + c] + bias[2 * HH + hcol];
        float vo = Gs[b * 68 + 48 + c] + bias[3 * HH + hcol];
        float ii = 1.f / (1.f + __expf(-vi));
        float ff = 1.f / (1.f + __expf(-vf));
        float gg = tanhf(vg);
        float oo = 1.f / (1.f + __expf(-vo));
        int idx = b * HH + hcol;
        float c2 = ff * c_state[idx] + ii * gg;
        c_state[idx] = c2;
        h_out[idx] = tf32r(oo * tanhf(c2));   // round: h re-enters tf32 GEMMs
    }
}

// ---------------- FC + hardtanh + feedback: one warp per (j, b) output --------
__global__ void __launch_bounds__(256)
fc_kernel(const float* __restrict__ h1,
          const float* __restrict__ fc_w,
          const float* __restrict__ fc_b,
          float* __restrict__ out, int t) {
    int gw = (blockIdx.x * blockDim.x + threadIdx.x) >> 5;
    int lane = threadIdx.x & 31;
    if (gw >= OUTD * BB) return;
    int b = gw & 63;
    int j = gw >> 6;
    const float4* w4 = reinterpret_cast<const float4*>(fc_w + (size_t)j * HH);
    const float4* h4 = reinterpret_cast<const float4*>(h1 + (size_t)b * HH);
    float s = 0.f;
    #pragma unroll 4
    for (int k = lane; k < HH / 4; k += 32) {
        float4 w = w4[k], h = h4[k];
        s += w.x * h.x + w.y * h.y + w.z * h.z + w.w * h.w;
    }
    #pragma unroll
    for (int o = 16; o; o >>= 1) s += __shfl_xor_sync(0xffffffffu, s, o);
    if (lane == 0) {
        float v = s + fc_b[j];
        v = fminf(fmaxf(v, -1.f), 1.f);                  // hardtanh
        out[(size_t)b * (TT * OUTD) + t * OUTD + j] = v; // [B,T,OUT]
        g_x[b * KPAD + j] = tf32r(v);                    // detached feedback
    }
}

// ---------------- launch ----------------
extern "C" void kernel_launch(void* const* d_in, const int* in_sizes, int n_in,
                              void* d_out, int out_size) {
    (void)in_sizes; (void)n_in; (void)out_size;
    const float* inputs  = (const float*)d_in[0];
    const float* hiddens = (const float*)d_in[1];
    const float* cells   = (const float*)d_in[2];
    const float* W_ih0   = (const float*)d_in[3];
    const float* W_hh0   = (const float*)d_in[4];
    const float* b_ih0   = (const float*)d_in[5];
    const float* b_hh0   = (const float*)d_in[6];
    const float* W_ih1   = (const float*)d_in[7];
    const float* W_hh1   = (const float*)d_in[8];
    const float* b_ih1   = (const float*)d_in[9];
    const float* b_hh1   = (const float*)d_in[10];
    const float* fc_w    = (const float*)d_in[11];
    const float* fc_b    = (const float*)d_in[12];
    float* out = (float*)d_out;

    float *p_Wih0p, *p_x, *p_b0, *p_b1, *p_h0a, *p_h0b, *p_h1a, *p_h1b, *p_c0, *p_c1;
    cudaGetSymbolAddress((void**)&p_Wih0p, g_Wih0p);
    cudaGetSymbolAddress((void**)&p_x,     g_x);
    cudaGetSymbolAddress((void**)&p_b0,    g_bias0);
    cudaGetSymbolAddress((void**)&p_b1,    g_bias1);
    cudaGetSymbolAddress((void**)&p_h0a,   g_h0a);
    cudaGetSymbolAddress((void**)&p_h0b,   g_h0b);
    cudaGetSymbolAddress((void**)&p_h1a,   g_h1a);
    cudaGetSymbolAddress((void**)&p_h1b,   g_h1b);
    cudaGetSymbolAddress((void**)&p_c0,    g_c0);
    cudaGetSymbolAddress((void**)&p_c1,    g_c1);

    setup_kernel<<<6240, 256>>>(inputs, hiddens, cells, W_ih0,
                                b_ih0, b_hh0, b_ih1, b_hh1);

    for (int t = 0; t < TT; t++) {
        float* h0_in  = (t & 1) ? p_h0b : p_h0a;
        float* h0_out = (t & 1) ? p_h0a : p_h0b;
        float* h1_in  = (t & 1) ? p_h1b : p_h1a;
        float* h1_out = (t & 1) ? p_h1a : p_h1b;
        lstm_cell_kernel<KPAD><<<128, 256>>>(p_x,    p_Wih0p, h0_in, W_hh0,
                                             p_b0, p_c0, h0_out);
        lstm_cell_kernel<HH><<<128, 256>>>(h0_out, W_ih1,  h1_in, W_hh1,
                                           p_b1, p_c1, h1_out);
        fc_kernel<<<528, 256>>>(h1_out, fc_w, fc_b, out, t);
    }
}

// round 3
// speedup vs baseline: 2.5794x; 2.5794x over previous
#include <cuda_runtime.h>
#include <cuda_fp16.h>
#include <cstdint>
#include <math.h>

#define BB   64
#define HH   2048
#define HIN  66
#define KPAD 128
#define TT   25
#define OUTD 66
#define G4   8192   // 4*H gate rows

// ---------------- device scratch (static globals; no allocation) ----------------
__device__ __align__(256) __half g_Wih0h[G4 * KPAD];  // padded 66 -> 128
__device__ __align__(256) __half g_Whh0h[G4 * HH];
__device__ __align__(256) __half g_Wih1h[G4 * HH];
__device__ __align__(256) __half g_Whh1h[G4 * HH];
__device__ __align__(256) __half g_x[BB * KPAD];      // fed-back input, padded
__device__ __align__(256) float  g_bias0[G4];
__device__ __align__(256) float  g_bias1[G4];
__device__ __align__(256) __half g_h0a[BB * HH], g_h0b[BB * HH];
__device__ __align__(256) __half g_h1a[BB * HH], g_h1b[BB * HH];
__device__ __align__(256) float  g_c0[BB * HH],  g_c1[BB * HH];

// ---------------- setup: fp32 -> fp16 weight conversion, bias fuse, state init --
__global__ void setup_kernel(const float* __restrict__ inputs,
                             const float* __restrict__ hiddens,
                             const float* __restrict__ cells,
                             const float* __restrict__ W_ih0,
                             const float* __restrict__ W_hh0,
                             const float* __restrict__ b_ih0,
                             const float* __restrict__ b_hh0,
                             const float* __restrict__ W_ih1,
                             const float* __restrict__ W_hh1,
                             const float* __restrict__ b_ih1,
                             const float* __restrict__ b_hh1) {
    int i = blockIdx.x * blockDim.x + threadIdx.x;
    const int V8 = G4 * HH / 8;          // 2097152 vec8 units per big weight
    if (i < 3 * V8) {                    // Whh0, Wih1, Whh1 (contiguous K=2048)
        int a = i / V8, j = i % V8;
        const float* src = (a == 0) ? W_hh0 : (a == 1) ? W_ih1 : W_hh1;
        __half* dst = (a == 0) ? g_Whh0h : (a == 1) ? g_Wih1h : g_Whh1h;
        float4 f0 = *reinterpret_cast<const float4*>(src + (size_t)j * 8);
        float4 f1 = *reinterpret_cast<const float4*>(src + (size_t)j * 8 + 4);
        uint4 u;
        *reinterpret_cast<__half2*>(&u.x) = __floats2half2_rn(f0.x, f0.y);
        *reinterpret_cast<__half2*>(&u.y) = __floats2half2_rn(f0.z, f0.w);
        *reinterpret_cast<__half2*>(&u.z) = __floats2half2_rn(f1.x, f1.y);
        *reinterpret_cast<__half2*>(&u.w) = __floats2half2_rn(f1.z, f1.w);
        reinterpret_cast<uint4*>(dst)[j] = u;
        return;
    }
    i -= 3 * V8;
    const int NW0v = G4 * KPAD / 8;      // 131072
    if (i < NW0v) {                      // W_ih0 pad 66->128
        int r = i >> 4, c8 = i & 15;
        __half tmp[8];
        #pragma unroll
        for (int e = 0; e < 8; e++) {
            int c = c8 * 8 + e;
            tmp[e] = __float2half(c < HIN ? W_ih0[r * HIN + c] : 0.f);
        }
        *reinterpret_cast<uint4*>(g_Wih0h + r * KPAD + c8 * 8) =
            *reinterpret_cast<uint4*>(tmp);
        return;
    }
    i -= NW0v;
    const int NXv = BB * KPAD / 8;       // 1024
    if (i < NXv) {                       // x pad
        int b = i >> 4, c8 = i & 15;
        __half tmp[8];
        #pragma unroll
        for (int e = 0; e < 8; e++) {
            int c = c8 * 8 + e;
            tmp[e] = __float2half(c < HIN ? inputs[b * HIN + c] : 0.f);
        }
        *reinterpret_cast<uint4*>(g_x + b * KPAD + c8 * 8) =
            *reinterpret_cast<uint4*>(tmp);
        return;
    }
    i -= NXv;
    if (i < G4) { g_bias0[i] = b_ih0[i] + b_hh0[i]; return; }
    i -= G4;
    if (i < G4) { g_bias1[i] = b_ih1[i] + b_hh1[i]; return; }
    i -= G4;
    const int NS = BB * HH;              // 131072
    if (i < NS) { g_h0a[i] = __float2half(hiddens[i]); return; }
    i -= NS;
    if (i < NS) { g_h1a[i] = __float2half(hiddens[NS + i]); return; }
    i -= NS;
    if (i < NS) { g_c0[i] = cells[i]; return; }
    i -= NS;
    if (i < NS) { g_c1[i] = cells[NS + i]; return; }
}

// ---------------- GEMM segment: acc += A[64,K] * W[rows,K]^T on a 64x64 tile ----
// cp.async double-buffered; m16n8k16 fp16 HMMA with fp32 accumulate.
// Block bn owns weight rows {gsec*H + bn*16 + r : gsec in 0..3, r in 0..15}.
template<int K>
__device__ __forceinline__ void gemm_seg(const __half* __restrict__ A,
                                         const __half* __restrict__ W,
                                         int bn, int tid, int wm, int wn,
                                         int g, int tg,
                                         float (&acc)[4][4],
                                         __half (&As)[2][64][72],
                                         __half (&Ws)[2][64][72]) {
    const int NT = K / 64;

    auto stage = [&](int tile, int buf) {
        int k0 = tile * 64;
        #pragma unroll
        for (int it = 0; it < 2; it++) {
            int chunk = tid + it * 256;
            int r = chunk >> 3, c8 = chunk & 7;
            uint32_t d = (uint32_t)__cvta_generic_to_shared(&As[buf][r][c8 * 8]);
            const __half* s = A + (size_t)r * K + k0 + c8 * 8;
            asm volatile("cp.async.cg.shared.global [%0], [%1], 16;\n"
                         :: "r"(d), "l"(s));
        }
        #pragma unroll
        for (int it = 0; it < 2; it++) {
            int chunk = tid + it * 256;
            int jj = chunk >> 3, c8 = chunk & 7;
            int wrow = (jj >> 4) * HH + bn * 16 + (jj & 15);
            uint32_t d = (uint32_t)__cvta_generic_to_shared(&Ws[buf][jj][c8 * 8]);
            const __half* s = W + (size_t)wrow * K + k0 + c8 * 8;
            asm volatile("cp.async.cg.shared.global [%0], [%1], 16;\n"
                         :: "r"(d), "l"(s));
        }
        asm volatile("cp.async.commit_group;\n");
    };

    stage(0, 0);
    for (int t = 0; t < NT; t++) {
        if (t + 1 < NT) {
            stage(t + 1, (t + 1) & 1);
            asm volatile("cp.async.wait_group 1;\n");
        } else {
            asm volatile("cp.async.wait_group 0;\n");
        }
        __syncthreads();
        int buf = t & 1;
        #pragma unroll
        for (int kk = 0; kk < 64; kk += 16) {
            uint32_t a0 = *reinterpret_cast<const uint32_t*>(&As[buf][wm * 16 + g][kk + tg * 2]);
            uint32_t a1 = *reinterpret_cast<const uint32_t*>(&As[buf][wm * 16 + g + 8][kk + tg * 2]);
            uint32_t a2 = *reinterpret_cast<const uint32_t*>(&As[buf][wm * 16 + g][kk + tg * 2 + 8]);
            uint32_t a3 = *reinterpret_cast<const uint32_t*>(&As[buf][wm * 16 + g + 8][kk + tg * 2 + 8]);
            #pragma unroll
            for (int nt = 0; nt < 4; nt++) {
                int col = wn * 32 + nt * 8 + g;
                uint32_t b0 = *reinterpret_cast<const uint32_t*>(&Ws[buf][col][kk + tg * 2]);
                uint32_t b1 = *reinterpret_cast<const uint32_t*>(&Ws[buf][col][kk + tg * 2 + 8]);
                asm volatile(
                    "mma.sync.aligned.m16n8k16.row.col.f32.f16.f16.f32 "
                    "{%0,%1,%2,%3}, {%4,%5,%6,%7}, {%8,%9}, {%0,%1,%2,%3};\n"
                    : "+f"(acc[nt][0]), "+f"(acc[nt][1]),
                      "+f"(acc[nt][2]), "+f"(acc[nt][3])
                    : "r"(a0), "r"(a1), "r"(a2), "r"(a3), "r"(b0), "r"(b1));
            }
        }
        __syncthreads();
    }
}

// ---------------- fused LSTM cell ----------------
// grid = 128 blocks (H/16 column tiles), 256 threads (8 warps: 4 M x 2 N)
template<int KI>
__global__ void __launch_bounds__(256, 1)
lstm_cell_kernel(const __half* __restrict__ actI,   // [BB, KI]
                 const __half* __restrict__ Wih,    // [G4, KI]
                 const __half* __restrict__ actH,   // [BB, HH]
                 const __half* __restrict__ Whh,    // [G4, HH]
                 const float* __restrict__ bias,    // [G4]
                 float* __restrict__ c_state,
                 __half* __restrict__ h_out) {
    __shared__ __align__(16) __half As[2][64][72];
    __shared__ __align__(16) __half Ws[2][64][72];
    const int tid  = threadIdx.x;
    const int lane = tid & 31;
    const int warp = tid >> 5;
    const int g  = lane >> 2, tg = lane & 3;
    const int wm = warp & 3,  wn = warp >> 2;
    const int bn = blockIdx.x;

    float acc[4][4];
    #pragma unroll
    for (int a = 0; a < 4; a++)
        #pragma unroll
        for (int b = 0; b < 4; b++) acc[a][b] = 0.f;

    gemm_seg<KI>(actI, Wih, bn, tid, wm, wn, g, tg, acc, As, Ws);
    gemm_seg<HH>(actH, Whh, bn, tid, wm, wn, g, tg, acc, As, Ws);

    // scatter C fragments to shared (reuse As storage as float, stride 68)
    float* Gs = reinterpret_cast<float*>(As);
    {
        int row = wm * 16 + g;
        #pragma unroll
        for (int nt = 0; nt < 4; nt++) {
            int col = wn * 32 + nt * 8 + tg * 2;
            Gs[row * 68 + col]           = acc[nt][0];
            Gs[row * 68 + col + 1]       = acc[nt][1];
            Gs[(row + 8) * 68 + col]     = acc[nt][2];
            Gs[(row + 8) * 68 + col + 1] = acc[nt][3];
        }
    }
    __syncthreads();

    // elementwise LSTM: gate sections i,f,g,o at tile cols 0,16,32,48
    #pragma unroll
    for (int it = 0; it < 4; it++) {
        int s = tid + it * 256;
        int b = s >> 4, c = s & 15;
        int hcol = bn * 16 + c;
        float vi = Gs[b * 68 + c]      + bias[hcol];
        float vf = Gs[b * 68 + 16 + c] + bias[HH + hcol];
        float vg = Gs[b * 68 + 32 + c] + bias[2 * HH + hcol];
        float vo = Gs[b * 68 + 48 + c] + bias[3 * HH + hcol];
        float ii = 1.f / (1.f + __expf(-vi));
        float ff = 1.f / (1.f + __expf(-vf));
        float gg = tanhf(vg);
        float oo = 1.f / (1.f + __expf(-vo));
        int idx = b * HH + hcol;
        float c2 = ff * c_state[idx] + ii * gg;
        c_state[idx] = c2;
        h_out[idx] = __float2half(oo * tanhf(c2));
    }
}

// ---------------- FC + hardtanh + feedback: one warp per (j, b) output --------
__global__ void __launch_bounds__(256)
fc_kernel(const __half* __restrict__ h1,
          const float* __restrict__ fc_w,
          const float* __restrict__ fc_b,
          float* __restrict__ out, int t) {
    int gw = (blockIdx.x * blockDim.x + threadIdx.x) >> 5;
    int lane = threadIdx.x & 31;
    if (gw >= OUTD * BB) return;
    int b = gw & 63;
    int j = gw >> 6;
    const float2*  w2 = reinterpret_cast<const float2*>(fc_w + (size_t)j * HH);
    const __half2* h2 = reinterpret_cast<const __half2*>(h1 + (size_t)b * HH);
    float s = 0.f;
    #pragma unroll 4
    for (int k = lane; k < HH / 2; k += 32) {
        float2 w = w2[k];
        float2 h = __half22float2(h2[k]);
        s += w.x * h.x + w.y * h.y;
    }
    #pragma unroll
    for (int o = 16; o; o >>= 1) s += __shfl_xor_sync(0xffffffffu, s, o);
    if (lane == 0) {
        float v = s + fc_b[j];
        v = fminf(fmaxf(v, -1.f), 1.f);                  // hardtanh
        out[(size_t)b * (TT * OUTD) + t * OUTD + j] = v; // [B,T,OUT]
        g_x[b * KPAD + j] = __float2half(v);             // detached feedback
    }
}

// ---------------- launch ----------------
extern "C" void kernel_launch(void* const* d_in, const int* in_sizes, int n_in,
                              void* d_out, int out_size) {
    (void)in_sizes; (void)n_in; (void)out_size;
    const float* inputs  = (const float*)d_in[0];
    const float* hiddens = (const float*)d_in[1];
    const float* cells   = (const float*)d_in[2];
    const float* W_ih0   = (const float*)d_in[3];
    const float* W_hh0   = (const float*)d_in[4];
    const float* b_ih0   = (const float*)d_in[5];
    const float* b_hh0   = (const float*)d_in[6];
    const float* W_ih1   = (const float*)d_in[7];
    const float* W_hh1   = (const float*)d_in[8];
    const float* b_ih1   = (const float*)d_in[9];
    const float* b_hh1   = (const float*)d_in[10];
    const float* fc_w    = (const float*)d_in[11];
    const float* fc_b    = (const float*)d_in[12];
    float* out = (float*)d_out;

    __half *p_Wih0h, *p_Whh0h, *p_Wih1h, *p_Whh1h, *p_x;
    __half *p_h0a, *p_h0b, *p_h1a, *p_h1b;
    float *p_b0, *p_b1, *p_c0, *p_c1;
    cudaGetSymbolAddress((void**)&p_Wih0h, g_Wih0h);
    cudaGetSymbolAddress((void**)&p_Whh0h, g_Whh0h);
    cudaGetSymbolAddress((void**)&p_Wih1h, g_Wih1h);
    cudaGetSymbolAddress((void**)&p_Whh1h, g_Whh1h);
    cudaGetSymbolAddress((void**)&p_x,     g_x);
    cudaGetSymbolAddress((void**)&p_b0,    g_bias0);
    cudaGetSymbolAddress((void**)&p_b1,    g_bias1);
    cudaGetSymbolAddress((void**)&p_h0a,   g_h0a);
    cudaGetSymbolAddress((void**)&p_h0b,   g_h0b);
    cudaGetSymbolAddress((void**)&p_h1a,   g_h1a);
    cudaGetSymbolAddress((void**)&p_h1b,   g_h1b);
    cudaGetSymbolAddress((void**)&p_c0,    g_c0);
    cudaGetSymbolAddress((void**)&p_c1,    g_c1);

    // total setup threads: 3*2097152 + 131072 + 1024 + 16384 + 4*131072 = 6964224
    setup_kernel<<<(6964224 + 255) / 256, 256>>>(inputs, hiddens, cells,
                                                 W_ih0, W_hh0, b_ih0, b_hh0,
                                                 W_ih1, W_hh1, b_ih1, b_hh1);

    for (int t = 0; t < TT; t++) {
        __half* h0_in  = (t & 1) ? p_h0b : p_h0a;
        __half* h0_out = (t & 1) ? p_h0a : p_h0b;
        __half* h1_in  = (t & 1) ? p_h1b : p_h1a;
        __half* h1_out = (t & 1) ? p_h1a : p_h1b;
        lstm_cell_kernel<KPAD><<<128, 256>>>(p_x, p_Wih0h, h0_in, p_Whh0h,
                                             p_b0, p_c0, h0_out);
        lstm_cell_kernel<HH><<<128, 256>>>(h0_out, p_Wih1h, h1_in, p_Whh1h,
                                           p_b1, p_c1, h1_out);
        fc_kernel<<<528, 256>>>(h1_out, fc_w, fc_b, out, t);
    }
}

// round 4
// speedup vs baseline: 3.0307x; 1.1749x over previous
#include <cuda_runtime.h>
#include <cuda_fp16.h>
#include <cstdint>
#include <math.h>

#define BB   64
#define HH   2048
#define HIN  66
#define KPAD 128
#define TT   25
#define OUTD 66
#define G4   8192
#define NCTA 128

// ---------------- device scratch ----------------
__device__ __align__(256) __half g_Wih0h[G4 * KPAD];
__device__ __align__(256) __half g_Whh0h[G4 * HH];
__device__ __align__(256) __half g_Wih1h[G4 * HH];
__device__ __align__(256) __half g_Whh1h[G4 * HH];
__device__ __align__(256) __half g_fcwh[OUTD * HH];
__device__ __align__(256) __half g_x[BB * KPAD];
__device__ __align__(256) float  g_bias0[G4];
__device__ __align__(256) float  g_bias1[G4];
__device__ __align__(256) __half g_h0a[BB * HH], g_h0b[BB * HH];
__device__ __align__(256) __half g_h1a[BB * HH], g_h1b[BB * HH];
__device__ __align__(256) float  g_c0[BB * HH],  g_c1[BB * HH];
__device__ unsigned g_barcnt;

// ---------------- setup ----------------
__global__ void setup_kernel(const float* __restrict__ inputs,
                             const float* __restrict__ hiddens,
                             const float* __restrict__ cells,
                             const float* __restrict__ W_ih0,
                             const float* __restrict__ W_hh0,
                             const float* __restrict__ b_ih0,
                             const float* __restrict__ b_hh0,
                             const float* __restrict__ W_ih1,
                             const float* __restrict__ W_hh1,
                             const float* __restrict__ b_ih1,
                             const float* __restrict__ b_hh1,
                             const float* __restrict__ fc_w) {
    int i = blockIdx.x * blockDim.x + threadIdx.x;
    if (i == 0) g_barcnt = 0;
    const int V8 = G4 * HH / 8;          // 2097152
    if (i < 3 * V8) {                    // Whh0, Wih1, Whh1
        int a = i / V8, j = i % V8;
        const float* src = (a == 0) ? W_hh0 : (a == 1) ? W_ih1 : W_hh1;
        __half* dst = (a == 0) ? g_Whh0h : (a == 1) ? g_Wih1h : g_Whh1h;
        float4 f0 = *reinterpret_cast<const float4*>(src + (size_t)j * 8);
        float4 f1 = *reinterpret_cast<const float4*>(src + (size_t)j * 8 + 4);
        uint4 u;
        *reinterpret_cast<__half2*>(&u.x) = __floats2half2_rn(f0.x, f0.y);
        *reinterpret_cast<__half2*>(&u.y) = __floats2half2_rn(f0.z, f0.w);
        *reinterpret_cast<__half2*>(&u.z) = __floats2half2_rn(f1.x, f1.y);
        *reinterpret_cast<__half2*>(&u.w) = __floats2half2_rn(f1.z, f1.w);
        reinterpret_cast<uint4*>(dst)[j] = u;
        return;
    }
    i -= 3 * V8;
    const int NW0v = G4 * KPAD / 8;      // 131072
    if (i < NW0v) {                      // W_ih0 pad 66->128
        int r = i >> 4, c8 = i & 15;
        __half tmp[8];
        #pragma unroll
        for (int e = 0; e < 8; e++) {
            int c = c8 * 8 + e;
            tmp[e] = __float2half(c < HIN ? W_ih0[r * HIN + c] : 0.f);
        }
        *reinterpret_cast<uint4*>(g_Wih0h + r * KPAD + c8 * 8) =
            *reinterpret_cast<uint4*>(tmp);
        return;
    }
    i -= NW0v;
    const int NXv = BB * KPAD / 8;       // 1024
    if (i < NXv) {
        int b = i >> 4, c8 = i & 15;
        __half tmp[8];
        #pragma unroll
        for (int e = 0; e < 8; e++) {
            int c = c8 * 8 + e;
            tmp[e] = __float2half(c < HIN ? inputs[b * HIN + c] : 0.f);
        }
        *reinterpret_cast<uint4*>(g_x + b * KPAD + c8 * 8) =
            *reinterpret_cast<uint4*>(tmp);
        return;
    }
    i -= NXv;
    if (i < G4) { g_bias0[i] = b_ih0[i] + b_hh0[i]; return; }
    i -= G4;
    if (i < G4) { g_bias1[i] = b_ih1[i] + b_hh1[i]; return; }
    i -= G4;
    const int NFC = OUTD * HH / 8;       // 16896
    if (i < NFC) {
        float4 f0 = *reinterpret_cast<const float4*>(fc_w + (size_t)i * 8);
        float4 f1 = *reinterpret_cast<const float4*>(fc_w + (size_t)i * 8 + 4);
        uint4 u;
        *reinterpret_cast<__half2*>(&u.x) = __floats2half2_rn(f0.x, f0.y);
        *reinterpret_cast<__half2*>(&u.y) = __floats2half2_rn(f0.z, f0.w);
        *reinterpret_cast<__half2*>(&u.z) = __floats2half2_rn(f1.x, f1.y);
        *reinterpret_cast<__half2*>(&u.w) = __floats2half2_rn(f1.z, f1.w);
        reinterpret_cast<uint4*>(g_fcwh)[i] = u;
        return;
    }
    i -= NFC;
    const int NS = BB * HH;              // 131072
    if (i < NS) { g_h0a[i] = __float2half(hiddens[i]); return; }
    i -= NS;
    if (i < NS) { g_h1a[i] = __float2half(hiddens[NS + i]); return; }
    i -= NS;
    if (i < NS) { g_c0[i] = cells[i]; return; }
    i -= NS;
    if (i < NS) { g_c1[i] = cells[NS + i]; return; }
}

// ---------------- software grid barrier (all 128 CTAs resident) ----------------
__device__ __forceinline__ void grid_bar(unsigned target) {
    __syncthreads();
    if (threadIdx.x == 0) {
        __threadfence();                       // release prior gmem writes
        atomicAdd(&g_barcnt, 1u);
        unsigned v;
        do {
            asm volatile("ld.acquire.gpu.u32 %0, [%1];" : "=r"(v)
                         : "l"(&g_barcnt) : "memory");
        } while (v < target);
    }
    __syncthreads();
}

// ---------------- stage one 64x64 tile pair via cp.async ----------------
// smem layout (halves): A stages at s*4608, W stages at 13824 + s*4608 (72 pitch)
__device__ __forceinline__ void stage_tile(__half* sm, int buf,
                                           const __half* __restrict__ A, int strideA,
                                           const __half* __restrict__ W, int strideW,
                                           int k0, int bn, int tid) {
    __half* as = sm + buf * 4608;
    __half* ws = sm + 13824 + buf * 4608;
    #pragma unroll
    for (int it = 0; it < 2; it++) {
        int chunk = tid + it * 256;
        int r = chunk >> 3, c8 = chunk & 7;
        uint32_t d = (uint32_t)__cvta_generic_to_shared(as + r * 72 + c8 * 8);
        const __half* s = A + (size_t)r * strideA + k0 + c8 * 8;
        asm volatile("cp.async.cg.shared.global [%0], [%1], 16;\n" :: "r"(d), "l"(s));
    }
    #pragma unroll
    for (int it = 0; it < 2; it++) {
        int chunk = tid + it * 256;
        int jj = chunk >> 3, c8 = chunk & 7;
        int wrow = (jj >> 4) * HH + bn * 16 + (jj & 15);
        uint32_t d = (uint32_t)__cvta_generic_to_shared(ws + jj * 72 + c8 * 8);
        const __half* s = W + (size_t)wrow * strideW + k0 + c8 * 8;
        asm volatile("cp.async.cg.shared.global [%0], [%1], 16;\n" :: "r"(d), "l"(s));
    }
    asm volatile("cp.async.commit_group;\n");
}

__device__ __forceinline__ void mma16816(float (&c)[4], uint32_t a0, uint32_t a1,
                                         uint32_t a2, uint32_t a3,
                                         uint32_t b0, uint32_t b1) {
    asm volatile(
        "mma.sync.aligned.m16n8k16.row.col.f32.f16.f16.f32 "
        "{%0,%1,%2,%3}, {%4,%5,%6,%7}, {%8,%9}, {%0,%1,%2,%3};\n"
        : "+f"(c[0]), "+f"(c[1]), "+f"(c[2]), "+f"(c[3])
        : "r"(a0), "r"(a1), "r"(a2), "r"(a3), "r"(b0), "r"(b1));
}

// ---------------- fused LSTM cell body: unified-pipeline dual GEMM + epilogue ---
template<int KI>
__device__ __forceinline__ void cell_body(__half* sm,
                                          const __half* __restrict__ actI,
                                          const __half* __restrict__ Wih,
                                          const __half* __restrict__ actH,
                                          const __half* __restrict__ Whh,
                                          const float* __restrict__ bias,
                                          float* __restrict__ c_state,
                                          __half* __restrict__ h_out,
                                          int bn, int tid) {
    const int NTI = KI / 64, NT = NTI + HH / 64;
    const int lane = tid & 31, warp = tid >> 5;
    const int wm = warp & 3, wn = warp >> 2;

    float acc[4][4];
    #pragma unroll
    for (int a = 0; a < 4; a++)
        #pragma unroll
        for (int b = 0; b < 4; b++) acc[a][b] = 0.f;

    auto stage = [&](int t) {
        if (t < NTI) stage_tile(sm, t % 3, actI, KI, Wih, KI, t * 64, bn, tid);
        else         stage_tile(sm, t % 3, actH, HH, Whh, HH, (t - NTI) * 64, bn, tid);
    };
    stage(0);
    stage(1);

    const int arow  = wm * 16 + (lane & 15);
    const int brow1 = wn * 32 + (lane & 15);
    const int khalf = (lane >> 4) * 8;

    for (int t = 0; t < NT; t++) {
        if (t + 2 < NT) {
            asm volatile("cp.async.wait_group 1;\n" ::: "memory");
            __syncthreads();
            stage(t + 2);
        } else {
            asm volatile("cp.async.wait_group 0;\n" ::: "memory");
            __syncthreads();
        }
        __half* as = sm + (t % 3) * 4608;
        __half* ws = sm + 13824 + (t % 3) * 4608;
        uint32_t abase  = (uint32_t)__cvta_generic_to_shared(as + arow  * 72 + khalf);
        uint32_t bbase1 = (uint32_t)__cvta_generic_to_shared(ws + brow1 * 72 + khalf);
        uint32_t bbase2 = bbase1 + 16 * 72 * 2;
        #pragma unroll
        for (int kk = 0; kk < 64; kk += 16) {
            uint32_t a0, a1, a2, a3, p0, p1, p2, p3, q0, q1, q2, q3;
            asm volatile("ldmatrix.sync.aligned.m8n8.x4.shared.b16 {%0,%1,%2,%3}, [%4];\n"
                         : "=r"(a0), "=r"(a1), "=r"(a2), "=r"(a3) : "r"(abase + kk * 2));
            asm volatile("ldmatrix.sync.aligned.m8n8.x4.shared.b16 {%0,%1,%2,%3}, [%4];\n"
                         : "=r"(p0), "=r"(p1), "=r"(p2), "=r"(p3) : "r"(bbase1 + kk * 2));
            asm volatile("ldmatrix.sync.aligned.m8n8.x4.shared.b16 {%0,%1,%2,%3}, [%4];\n"
                         : "=r"(q0), "=r"(q1), "=r"(q2), "=r"(q3) : "r"(bbase2 + kk * 2));
            mma16816(acc[0], a0, a1, a2, a3, p0, p2);
            mma16816(acc[1], a0, a1, a2, a3, p1, p3);
            mma16816(acc[2], a0, a1, a2, a3, q0, q2);
            mma16816(acc[3], a0, a1, a2, a3, q1, q3);
        }
    }
    __syncthreads();

    // scatter fragments to shared (float overlay on A-stage region, pitch 68)
    float* Gs = reinterpret_cast<float*>(sm);
    {
        int row = wm * 16 + (lane >> 2);
        int col0 = wn * 32 + (lane & 3) * 2;
        #pragma unroll
        for (int nt = 0; nt < 4; nt++) {
            int col = col0 + nt * 8;
            Gs[row * 68 + col]           = acc[nt][0];
            Gs[row * 68 + col + 1]       = acc[nt][1];
            Gs[(row + 8) * 68 + col]     = acc[nt][2];
            Gs[(row + 8) * 68 + col + 1] = acc[nt][3];
        }
    }
    __syncthreads();

    #pragma unroll
    for (int it = 0; it < 4; it++) {
        int s = tid + it * 256;
        int b = s >> 4, c = s & 15;
        int hcol = bn * 16 + c;
        float vi = Gs[b * 68 + c]      + bias[hcol];
        float vf = Gs[b * 68 + 16 + c] + bias[HH + hcol];
        float vg = Gs[b * 68 + 32 + c] + bias[2 * HH + hcol];
        float vo = Gs[b * 68 + 48 + c] + bias[3 * HH + hcol];
        float ii = 1.f / (1.f + __expf(-vi));
        float ff = 1.f / (1.f + __expf(-vf));
        float gg = tanhf(vg);
        float oo = 1.f / (1.f + __expf(-vo));
        int idx = b * HH + hcol;
        float c2 = ff * c_state[idx] + ii * gg;
        c_state[idx] = c2;
        h_out[idx] = __float2half(oo * tanhf(c2));
    }
}

// ---------------- fc phase: warp per (j, b), fp16 both sides ----------------
__device__ __forceinline__ void fc_phase(const __half* __restrict__ h1,
                                         const __half* __restrict__ fcw,
                                         const float* __restrict__ fc_b,
                                         float* __restrict__ out,
                                         int t, int tid, int bid) {
    int gw = bid * 8 + (tid >> 5);
    int lane = tid & 31;
    for (int task = gw; task < OUTD * BB; task += NCTA * 8) {
        int j = task % OUTD, b = task / OUTD;
        const uint4* w4 = reinterpret_cast<const uint4*>(fcw + (size_t)j * HH);
        const uint4* h4 = reinterpret_cast<const uint4*>(h1 + (size_t)b * HH);
        float s = 0.f;
        #pragma unroll
        for (int it = 0; it < 8; it++) {
            int k = lane + it * 32;
            uint4 wu = w4[k], hu = h4[k];
            const __half2* wp = reinterpret_cast<const __half2*>(&wu);
            const __half2* hp = reinterpret_cast<const __half2*>(&hu);
            #pragma unroll
            for (int e = 0; e < 4; e++) {
                float2 wf = __half22float2(wp[e]);
                float2 hf = __half22float2(hp[e]);
                s += wf.x * hf.x + wf.y * hf.y;
            }
        }
        #pragma unroll
        for (int o = 16; o; o >>= 1) s += __shfl_xor_sync(0xffffffffu, s, o);
        if (lane == 0) {
            float v = s + fc_b[j];
            v = fminf(fmaxf(v, -1.f), 1.f);
            out[(size_t)b * (TT * OUTD) + t * OUTD + j] = v;
            g_x[b * KPAD + j] = __float2half(v);
        }
    }
}

// ---------------- one full step: cell0 | bar | cell1 | bar | fc ----------------
__global__ void __launch_bounds__(256, 1)
step_kernel(const __half* __restrict__ Wih0, const __half* __restrict__ Whh0,
            const __half* __restrict__ Wih1, const __half* __restrict__ Whh1,
            const float* __restrict__ b0, const float* __restrict__ b1,
            __half* h0_in, __half* h0_out, __half* h1_in, __half* h1_out,
            float* c0, float* c1,
            const __half* __restrict__ fcw, const float* __restrict__ fc_b,
            float* __restrict__ out, int t) {
    extern __shared__ __half sm[];
    int tid = threadIdx.x, bn = blockIdx.x;
    cell_body<KPAD>(sm, g_x, Wih0, h0_in, Whh0, b0, c0, h0_out, bn, tid);
    grid_bar((unsigned)(2 * t + 1) * NCTA);
    cell_body<HH>(sm, h0_out, Wih1, h1_in, Whh1, b1, c1, h1_out, bn, tid);
    grid_bar((unsigned)(2 * t + 2) * NCTA);
    fc_phase(h1_out, fcw, fc_b, out, t, tid, bn);
}

// ---------------- launch ----------------
extern "C" void kernel_launch(void* const* d_in, const int* in_sizes, int n_in,
                              void* d_out, int out_size) {
    (void)in_sizes; (void)n_in; (void)out_size;
    const float* inputs  = (const float*)d_in[0];
    const float* hiddens = (const float*)d_in[1];
    const float* cells   = (const float*)d_in[2];
    const float* W_ih0   = (const float*)d_in[3];
    const float* W_hh0   = (const float*)d_in[4];
    const float* b_ih0   = (const float*)d_in[5];
    const float* b_hh0   = (const float*)d_in[6];
    const float* W_ih1   = (const float*)d_in[7];
    const float* W_hh1   = (const float*)d_in[8];
    const float* b_ih1   = (const float*)d_in[9];
    const float* b_hh1   = (const float*)d_in[10];
    const float* fc_w    = (const float*)d_in[11];
    const float* fc_b    = (const float*)d_in[12];
    float* out = (float*)d_out;

    __half *p_Wih0h, *p_Whh0h, *p_Wih1h, *p_Whh1h, *p_fcwh;
    __half *p_h0a, *p_h0b, *p_h1a, *p_h1b;
    float *p_b0, *p_b1, *p_c0, *p_c1;
    cudaGetSymbolAddress((void**)&p_Wih0h, g_Wih0h);
    cudaGetSymbolAddress((void**)&p_Whh0h, g_Whh0h);
    cudaGetSymbolAddress((void**)&p_Wih1h, g_Wih1h);
    cudaGetSymbolAddress((void**)&p_Whh1h, g_Whh1h);
    cudaGetSymbolAddress((void**)&p_fcwh,  g_fcwh);
    cudaGetSymbolAddress((void**)&p_b0,    g_bias0);
    cudaGetSymbolAddress((void**)&p_b1,    g_bias1);
    cudaGetSymbolAddress((void**)&p_h0a,   g_h0a);
    cudaGetSymbolAddress((void**)&p_h0b,   g_h0b);
    cudaGetSymbolAddress((void**)&p_h1a,   g_h1a);
    cudaGetSymbolAddress((void**)&p_h1b,   g_h1b);
    cudaGetSymbolAddress((void**)&p_c0,    g_c0);
    cudaGetSymbolAddress((void**)&p_c1,    g_c1);

    // 128 KB dynamic smem -> guaranteed 1 CTA/SM (all 128 CTAs co-resident)
    static const int SMEM_BYTES = 131072;
    cudaFuncSetAttribute(step_kernel,
                         cudaFuncAttributeMaxDynamicSharedMemorySize, SMEM_BYTES);

    // total setup threads: 6291456+131072+1024+8192+8192+16896+4*131072 = 6981120
    setup_kernel<<<(6981120 + 255) / 256, 256>>>(inputs, hiddens, cells,
                                                 W_ih0, W_hh0, b_ih0, b_hh0,
                                                 W_ih1, W_hh1, b_ih1, b_hh1, fc_w);

    for (int t = 0; t < TT; t++) {
        __half* h0_in  = (t & 1) ? p_h0b : p_h0a;
        __half* h0_out = (t & 1) ? p_h0a : p_h0b;
        __half* h1_in  = (t & 1) ? p_h1b : p_h1a;
        __half* h1_out = (t & 1) ? p_h1a : p_h1b;
        step_kernel<<<NCTA, 256, SMEM_BYTES>>>(p_Wih0h, p_Whh0h, p_Wih1h, p_Whh1h,
                                               p_b0, p_b1,
                                               h0_in, h0_out, h1_in, h1_out,
                                               p_c0, p_c1,
                                               p_fcwh, fc_b, out, t);
    }
}

// round 5
// speedup vs baseline: 3.7068x; 1.2231x over previous
#include <cuda_runtime.h>
#include <cuda_fp16.h>
#include <cstdint>
#include <math.h>

#define BB   64
#define HH   2048
#define HIN  66
#define KPAD 128
#define TT   25
#define OUTD 66
#define G4   8192
#define NCTA 128
#define NST  6          // pipeline stages
#define NT0I 2          // cell0 input k-tiles (KPAD/64)
#define NT0  34         // cell0 total tiles
#define NT1I 32
#define NT1  64
#define TILE_H 4096     // halves per 64x64 tile

// ---------------- device scratch ----------------
// packed, swizzled weights: [bn][tile][jj(64)][swz-k(64)]
__device__ __align__(256) __half g_W0p[NCTA * NT0 * TILE_H];   // 34 MB
__device__ __align__(256) __half g_W1p[NCTA * NT1 * TILE_H];   // 64 MB
// activations: transposed + swizzled tile layout [ktile][r(64)][swz-b(64)]
__device__ __align__(256) __half g_xT[2 * TILE_H];
__device__ __align__(256) __half g_h0Ta[32 * TILE_H], g_h0Tb[32 * TILE_H];
__device__ __align__(256) __half g_h1Ta[32 * TILE_H], g_h1Tb[32 * TILE_H];
__device__ __align__(256) __half g_h1lin[BB * HH];             // for fc
__device__ __align__(256) __half g_fcwh[OUTD * HH];
__device__ __align__(256) float  g_bias0[G4], g_bias1[G4];
__device__ __align__(256) float  g_c0[BB * HH], g_c1[BB * HH];
__device__ unsigned g_barcnt;

// swizzled half-offset inside a 64x64 tile for (row, col8unit, elem)
__device__ __forceinline__ int swz_off(int row, int u, int e) {
    return row * 64 + ((u ^ (row & 7)) << 3) + e;
}

// ---------------- setup: pack + swizzle everything ----------------
__global__ void setup_kernel(const float* __restrict__ inputs,
                             const float* __restrict__ hiddens,
                             const float* __restrict__ cells,
                             const float* __restrict__ W_ih0,
                             const float* __restrict__ W_hh0,
                             const float* __restrict__ b_ih0,
                             const float* __restrict__ b_hh0,
                             const float* __restrict__ W_ih1,
                             const float* __restrict__ W_hh1,
                             const float* __restrict__ b_ih1,
                             const float* __restrict__ b_hh1,
                             const float* __restrict__ fc_w) {
    int i = blockIdx.x * blockDim.x + threadIdx.x;
    if (i == 0) g_barcnt = 0;

    const int S1 = NCTA * NT0 * 512;       // 2228224 vec8 units, W0 pack
    if (i < S1) {
        int bn = i / (NT0 * 512), r1 = i % (NT0 * 512);
        int T = r1 / 512, r2 = r1 & 511;
        int jj = r2 >> 3, u = r2 & 7;
        int R = (jj >> 4) * HH + bn * 16 + (jj & 15);
        __half tmp[8];
        if (T < NT0I) {
            #pragma unroll
            for (int e = 0; e < 8; e++) {
                int c = T * 64 + u * 8 + e;
                tmp[e] = __float2half(c < HIN ? W_ih0[(size_t)R * HIN + c] : 0.f);
            }
        } else {
            const float* s = W_hh0 + (size_t)R * HH + (T - NT0I) * 64 + u * 8;
            #pragma unroll
            for (int e = 0; e < 8; e++) tmp[e] = __float2half(s[e]);
        }
        size_t dst = ((size_t)(bn * NT0 + T) * 64 + jj) * 64 + ((u ^ (jj & 7)) << 3);
        *reinterpret_cast<uint4*>(g_W0p + dst) = *reinterpret_cast<uint4*>(tmp);
        return;
    }
    i -= S1;
    const int S2 = NCTA * NT1 * 512;       // 4194304, W1 pack
    if (i < S2) {
        int bn = i / (NT1 * 512), r1 = i % (NT1 * 512);
        int T = r1 / 512, r2 = r1 & 511;
        int jj = r2 >> 3, u = r2 & 7;
        int R = (jj >> 4) * HH + bn * 16 + (jj & 15);
        const float* s = (T < NT1I)
            ? W_ih1 + (size_t)R * HH + T * 64 + u * 8
            : W_hh1 + (size_t)R * HH + (T - NT1I) * 64 + u * 8;
        __half tmp[8];
        #pragma unroll
        for (int e = 0; e < 8; e++) tmp[e] = __float2half(s[e]);
        size_t dst = ((size_t)(bn * NT1 + T) * 64 + jj) * 64 + ((u ^ (jj & 7)) << 3);
        *reinterpret_cast<uint4*>(g_W1p + dst) = *reinterpret_cast<uint4*>(tmp);
        return;
    }
    i -= S2;
    const int S3 = 2 * 512;                // xT
    if (i < S3) {
        int kt = i / 512, r2 = i % 512;
        int r = r2 >> 3, u = r2 & 7;
        int j = kt * 64 + r;
        __half tmp[8];
        #pragma unroll
        for (int e = 0; e < 8; e++) {
            int b = u * 8 + e;
            tmp[e] = __float2half(j < HIN ? inputs[b * HIN + j] : 0.f);
        }
        *reinterpret_cast<uint4*>(g_xT + kt * TILE_H + swz_off(r, u, 0)) =
            *reinterpret_cast<uint4*>(tmp);
        return;
    }
    i -= S3;
    const int S4 = 32 * 512;               // h0Ta
    if (i < S4) {
        int kt = i / 512, r2 = i % 512;
        int r = r2 >> 3, u = r2 & 7;
        int j = kt * 64 + r;
        __half tmp[8];
        #pragma unroll
        for (int e = 0; e < 8; e++)
            tmp[e] = __float2half(hiddens[(size_t)(u * 8 + e) * HH + j]);
        *reinterpret_cast<uint4*>(g_h0Ta + kt * TILE_H + swz_off(r, u, 0)) =
            *reinterpret_cast<uint4*>(tmp);
        return;
    }
    i -= S4;
    if (i < S4) {                          // h1Ta
        int kt = i / 512, r2 = i % 512;
        int r = r2 >> 3, u = r2 & 7;
        int j = kt * 64 + r;
        __half tmp[8];
        #pragma unroll
        for (int e = 0; e < 8; e++)
            tmp[e] = __float2half(hiddens[(size_t)BB * HH + (size_t)(u * 8 + e) * HH + j]);
        *reinterpret_cast<uint4*>(g_h1Ta + kt * TILE_H + swz_off(r, u, 0)) =
            *reinterpret_cast<uint4*>(tmp);
        return;
    }
    i -= S4;
    if (i < G4) { g_bias0[i] = b_ih0[i] + b_hh0[i]; return; }
    i -= G4;
    if (i < G4) { g_bias1[i] = b_ih1[i] + b_hh1[i]; return; }
    i -= G4;
    const int S7 = OUTD * HH / 8;          // 16896, fcw
    if (i < S7) {
        float4 f0 = *reinterpret_cast<const float4*>(fc_w + (size_t)i * 8);
        float4 f1 = *reinterpret_cast<const float4*>(fc_w + (size_t)i * 8 + 4);
        uint4 u;
        *reinterpret_cast<__half2*>(&u.x) = __floats2half2_rn(f0.x, f0.y);
        *reinterpret_cast<__half2*>(&u.y) = __floats2half2_rn(f0.z, f0.w);
        *reinterpret_cast<__half2*>(&u.z) = __floats2half2_rn(f1.x, f1.y);
        *reinterpret_cast<__half2*>(&u.w) = __floats2half2_rn(f1.z, f1.w);
        reinterpret_cast<uint4*>(g_fcwh)[i] = u;
        return;
    }
    i -= S7;
    const int S8 = BB * HH / 4;            // 32768, c0
    if (i < S8) {
        reinterpret_cast<float4*>(g_c0)[i] =
            reinterpret_cast<const float4*>(cells)[i];
        return;
    }
    i -= S8;
    if (i < S8) {
        reinterpret_cast<float4*>(g_c1)[i] =
            reinterpret_cast<const float4*>(cells + (size_t)BB * HH)[i];
        return;
    }
}

// ---------------- software grid barrier ----------------
__device__ __forceinline__ void grid_bar(unsigned target) {
    __syncthreads();
    if (threadIdx.x == 0) {
        __threadfence();
        atomicAdd(&g_barcnt, 1u);
        unsigned v;
        do {
            asm volatile("ld.acquire.gpu.u32 %0, [%1];" : "=r"(v)
                         : "l"(&g_barcnt) : "memory");
        } while (v < target);
    }
    __syncthreads();
}

// ---------------- mbarrier primitives ----------------
__device__ __forceinline__ void mbar_init(uint32_t bar, uint32_t cnt) {
    asm volatile("mbarrier.init.shared.b64 [%0], %1;" :: "r"(bar), "r"(cnt) : "memory");
}
__device__ __forceinline__ void mbar_expect_tx(uint32_t bar, uint32_t bytes) {
    asm volatile("mbarrier.arrive.expect_tx.shared.b64 _, [%0], %1;"
                 :: "r"(bar), "r"(bytes) : "memory");
}
__device__ __forceinline__ void bulk_g2s(uint32_t dst, const void* src,
                                         uint32_t bytes, uint32_t bar) {
    asm volatile("cp.async.bulk.shared::cluster.global.mbarrier::complete_tx::bytes "
                 "[%0], [%1], %2, [%3];"
                 :: "r"(dst), "l"(src), "r"(bytes), "r"(bar) : "memory");
}
__device__ __forceinline__ void mbar_wait(uint32_t bar, uint32_t parity) {
    asm volatile(
        "{\n\t.reg .pred P;\n"
        "W%=:\n\t"
        "mbarrier.try_wait.parity.acquire.cta.shared::cta.b64 P, [%0], %1, 0x989680;\n\t"
        "@P bra D%=;\n\t"
        "bra W%=;\n"
        "D%=:\n\t}"
        :: "r"(bar), "r"(parity) : "memory");
}

__device__ __forceinline__ void mma16816(float (&c)[4], uint32_t a0, uint32_t a1,
                                         uint32_t a2, uint32_t a3,
                                         uint32_t b0, uint32_t b1) {
    asm volatile(
        "mma.sync.aligned.m16n8k16.row.col.f32.f16.f16.f32 "
        "{%0,%1,%2,%3}, {%4,%5,%6,%7}, {%8,%9}, {%0,%1,%2,%3};\n"
        : "+f"(c[0]), "+f"(c[1]), "+f"(c[2]), "+f"(c[3])
        : "r"(a0), "r"(a1), "r"(a2), "r"(a3), "r"(b0), "r"(b1));
}

// ---------------- fused LSTM cell body ----------------
// smem stages: stage s at byte s*16384 (A 8KB | W 8KB); barriers at 98304.
template<bool WRITE_LIN>
__device__ __forceinline__ void cell_body(char* smc, uint32_t smb,
                                          int tbase, int NTI, int NT,
                                          const __half* __restrict__ A0,
                                          const __half* __restrict__ A1,
                                          const __half* __restrict__ Wp,
                                          const float* __restrict__ bias,
                                          float* __restrict__ c_state,
                                          __half* __restrict__ hT_out,
                                          __half* __restrict__ h_lin,
                                          int bn, int tid) {
    const int lane = tid & 31, warp = tid >> 5;
    const int wm = warp & 3, wn = warp >> 2;
    const uint32_t barb = smb + NST * 16384;

    float acc[4][4];
    #pragma unroll
    for (int a = 0; a < 4; a++)
        #pragma unroll
        for (int b = 0; b < 4; b++) acc[a][b] = 0.f;

    auto issue = [&](int t) {
        int s = (tbase + t) % NST;
        uint32_t bar = barb + s * 8;
        mbar_expect_tx(bar, 16384);
        const __half* asrc = (t < NTI) ? A0 + (size_t)t * TILE_H
                                       : A1 + (size_t)(t - NTI) * TILE_H;
        bulk_g2s(smb + s * 16384, asrc, 8192, bar);
        bulk_g2s(smb + s * 16384 + 8192, Wp + (size_t)t * TILE_H, 8192, bar);
    };

    if (tid == 0) {
        #pragma unroll
        for (int p = 0; p < NST; p++) issue(p);
    }

    // per-lane constant addressing
    const int q = lane >> 3;
    const int kbA = (q >> 1) * 8 + (lane & 7);            // A k-row base
    const int mcol = wm * 16 + (q & 1) * 8;
    const int swzA = (((mcol >> 3) ^ (kbA & 7)) << 3);    // halves
    const int jjL = wn * 32 + (lane & 15);
    const int klane = lane >> 4;
    const int jmask = jjL & 7;

    for (int t = 0; t < NT; t++) {
        int tg = tbase + t;
        int s = tg % NST;
        mbar_wait(barb + s * 8, (tg / NST) & 1);
        uint32_t abuf = smb + s * 16384;
        uint32_t wbuf = abuf + 8192;
        #pragma unroll
        for (int kk = 0; kk < 64; kk += 16) {
            uint32_t aaddr = abuf + ((kk + kbA) << 7) + (swzA << 1);
            uint32_t waddr1 = wbuf + (jjL << 7)
                            + ((((klane + (kk >> 3)) ^ jmask) << 3) << 1);
            uint32_t waddr2 = waddr1 + (16 << 7);
            uint32_t a0, a1, a2, a3, p0, p1, p2, p3, q0, q1, q2, q3;
            asm volatile("ldmatrix.sync.aligned.m8n8.x4.trans.shared.b16 "
                         "{%0,%1,%2,%3}, [%4];\n"
                         : "=r"(a0), "=r"(a1), "=r"(a2), "=r"(a3) : "r"(aaddr));
            asm volatile("ldmatrix.sync.aligned.m8n8.x4.shared.b16 "
                         "{%0,%1,%2,%3}, [%4];\n"
                         : "=r"(p0), "=r"(p1), "=r"(p2), "=r"(p3) : "r"(waddr1));
            asm volatile("ldmatrix.sync.aligned.m8n8.x4.shared.b16 "
                         "{%0,%1,%2,%3}, [%4];\n"
                         : "=r"(q0), "=r"(q1), "=r"(q2), "=r"(q3) : "r"(waddr2));
            mma16816(acc[0], a0, a1, a2, a3, p0, p2);
            mma16816(acc[1], a0, a1, a2, a3, p1, p3);
            mma16816(acc[2], a0, a1, a2, a3, q0, q2);
            mma16816(acc[3], a0, a1, a2, a3, q1, q3);
        }
        __syncthreads();
        if (tid == 0 && t + NST < NT) issue(t + NST);
    }

    // epilogue: fragments -> smem scratch (overlay stage 0/1; pipeline drained)
    float* Gs = reinterpret_cast<float*>(smc);
    {
        int row = wm * 16 + (lane >> 2);
        int col0 = wn * 32 + (lane & 3) * 2;
        #pragma unroll
        for (int nt = 0; nt < 4; nt++) {
            int col = col0 + nt * 8;
            Gs[row * 68 + col]           = acc[nt][0];
            Gs[row * 68 + col + 1]       = acc[nt][1];
            Gs[(row + 8) * 68 + col]     = acc[nt][2];
            Gs[(row + 8) * 68 + col + 1] = acc[nt][3];
        }
    }
    __syncthreads();

    #pragma unroll
    for (int it = 0; it < 4; it++) {
        int sidx = tid + it * 256;
        int b = sidx >> 4, c = sidx & 15;
        int hcol = bn * 16 + c;
        float vi = Gs[b * 68 + c]      + bias[hcol];
        float vf = Gs[b * 68 + 16 + c] + bias[HH + hcol];
        float vg = Gs[b * 68 + 32 + c] + bias[2 * HH + hcol];
        float vo = Gs[b * 68 + 48 + c] + bias[3 * HH + hcol];
        float ii = 1.f / (1.f + __expf(-vi));
        float ff = 1.f / (1.f + __expf(-vf));
        float gg = tanhf(vg);
        float oo = 1.f / (1.f + __expf(-vo));
        int idx = b * HH + hcol;
        float c2 = ff * c_state[idx] + ii * gg;
        c_state[idx] = c2;
        __half hv = __float2half(oo * tanhf(c2));
        int kt = hcol >> 6, r = hcol & 63;
        hT_out[kt * TILE_H + swz_off(r, b >> 3, b & 7)] = hv;
        if (WRITE_LIN) h_lin[idx] = hv;
    }
    __syncthreads();
}

// ---------------- fc phase ----------------
__device__ __forceinline__ void fc_phase(const __half* __restrict__ h1,
                                         const __half* __restrict__ fcw,
                                         const float* __restrict__ fc_b,
                                         float* __restrict__ out,
                                         int t, int tid, int bid) {
    int gw = bid * 8 + (tid >> 5);
    int lane = tid & 31;
    for (int task = gw; task < OUTD * BB; task += NCTA * 8) {
        int j = task % OUTD, b = task / OUTD;
        const uint4* w4 = reinterpret_cast<const uint4*>(fcw + (size_t)j * HH);
        const uint4* h4 = reinterpret_cast<const uint4*>(h1 + (size_t)b * HH);
        float s = 0.f;
        #pragma unroll
        for (int it = 0; it < 8; it++) {
            int k = lane + it * 32;
            uint4 wu = w4[k], hu = h4[k];
            const __half2* wp = reinterpret_cast<const __half2*>(&wu);
            const __half2* hp = reinterpret_cast<const __half2*>(&hu);
            #pragma unroll
            for (int e = 0; e < 4; e++) {
                float2 wf = __half22float2(wp[e]);
                float2 hf = __half22float2(hp[e]);
                s += wf.x * hf.x + wf.y * hf.y;
            }
        }
        #pragma unroll
        for (int o = 16; o; o >>= 1) s += __shfl_xor_sync(0xffffffffu, s, o);
        if (lane == 0) {
            float v = s + fc_b[j];
            v = fminf(fmaxf(v, -1.f), 1.f);
            out[(size_t)b * (TT * OUTD) + t * OUTD + j] = v;
            int kt = j >> 6, r = j & 63;
            g_xT[kt * TILE_H + swz_off(r, b >> 3, b & 7)] = __float2half(v);
        }
    }
}

// ---------------- one full step ----------------
__global__ void __launch_bounds__(256, 1)
step_kernel(const __half* __restrict__ h0T_in, __half* __restrict__ h0T_out,
            const __half* __restrict__ h1T_in, __half* __restrict__ h1T_out,
            const float* __restrict__ fc_b, float* __restrict__ out, int t) {
    extern __shared__ char smc[];
    uint32_t smb = (uint32_t)__cvta_generic_to_shared(smc);
    int tid = threadIdx.x, bn = blockIdx.x;

    if (tid == 0) {
        #pragma unroll
        for (int s = 0; s < NST; s++) mbar_init(smb + NST * 16384 + s * 8, 1);
    }
    __syncthreads();

    cell_body<false>(smc, smb, 0, NT0I, NT0,
                     g_xT, h0T_in, g_W0p + (size_t)bn * NT0 * TILE_H,
                     g_bias0, g_c0, h0T_out, nullptr, bn, tid);
    grid_bar((unsigned)(2 * t + 1) * NCTA);
    cell_body<true>(smc, smb, NT0, NT1I, NT1,
                    h0T_out, h1T_in, g_W1p + (size_t)bn * NT1 * TILE_H,
                    g_bias1, g_c1, h1T_out, g_h1lin, bn, tid);
    grid_bar((unsigned)(2 * t + 2) * NCTA);
    fc_phase(g_h1lin, g_fcwh, fc_b, out, t, tid, bn);
}

// ---------------- launch ----------------
extern "C" void kernel_launch(void* const* d_in, const int* in_sizes, int n_in,
                              void* d_out, int out_size) {
    (void)in_sizes; (void)n_in; (void)out_size;
    const float* inputs  = (const float*)d_in[0];
    const float* hiddens = (const float*)d_in[1];
    const float* cells   = (const float*)d_in[2];
    const float* W_ih0   = (const float*)d_in[3];
    const float* W_hh0   = (const float*)d_in[4];
    const float* b_ih0   = (const float*)d_in[5];
    const float* b_hh0   = (const float*)d_in[6];
    const float* W_ih1   = (const float*)d_in[7];
    const float* W_hh1   = (const float*)d_in[8];
    const float* b_ih1   = (const float*)d_in[9];
    const float* b_hh1   = (const float*)d_in[10];
    const float* fc_w    = (const float*)d_in[11];
    const float* fc_b    = (const float*)d_in[12];
    float* out = (float*)d_out;

    __half *p_h0a, *p_h0b, *p_h1a, *p_h1b;
    cudaGetSymbolAddress((void**)&p_h0a, g_h0Ta);
    cudaGetSymbolAddress((void**)&p_h0b, g_h0Tb);
    cudaGetSymbolAddress((void**)&p_h1a, g_h1Ta);
    cudaGetSymbolAddress((void**)&p_h1b, g_h1Tb);

    static const int SMEM_BYTES = NST * 16384 + 1024;   // stages + barriers/pad
    cudaFuncSetAttribute(step_kernel,
                         cudaFuncAttributeMaxDynamicSharedMemorySize, SMEM_BYTES);

    // setup threads: 2228224+4194304+1024+16384+16384+8192+8192+16896+32768+32768
    const long SETUP_N = 6555136;
    setup_kernel<<<(int)((SETUP_N + 255) / 256), 256>>>(
        inputs, hiddens, cells, W_ih0, W_hh0, b_ih0, b_hh0,
        W_ih1, W_hh1, b_ih1, b_hh1, fc_w);

    for (int t = 0; t < TT; t++) {
        __half* h0_in  = (t & 1) ? p_h0b : p_h0a;
        __half* h0_out = (t & 1) ? p_h0a : p_h0b;
        __half* h1_in  = (t & 1) ? p_h1b : p_h1a;
        __half* h1_out = (t & 1) ? p_h1a : p_h1b;
        step_kernel<<<NCTA, 256, SMEM_BYTES>>>(h0_in, h0_out, h1_in, h1_out,
                                               fc_b, out, t);
    }
}

// round 7
// speedup vs baseline: 3.9208x; 1.0577x over previous
#include <cuda_runtime.h>
#include <cuda_fp16.h>
#include <cstdint>
#include <math.h>

#define BB   64
#define HH   2048
#define HIN  66
#define TT   25
#define OUTD 66
#define G4   8192
#define NCTA 128
#define NTHR 512
#define NST  6          // pipeline stages
#define NT0I 2          // cell0 input k-tiles
#define NT0  34         // cell0 total tiles
#define NT1I 32
#define NT1  64
#define TILE_H 4096     // halves per 64x64 tile

// ---------------- device scratch ----------------
// packed, swizzled weights: [bn][tile][jj(64)][swz-k(64)]
__device__ __align__(256) __half g_W0p[NCTA * NT0 * TILE_H];   // 34 MB
__device__ __align__(256) __half g_W1p[NCTA * NT1 * TILE_H];   // 64 MB
// activations: transposed + swizzled tile layout [ktile][r(64)][swz-b(64)]
__device__ __align__(256) __half g_xT[2 * TILE_H];
__device__ __align__(256) __half g_h0Ta[32 * TILE_H], g_h0Tb[32 * TILE_H];
__device__ __align__(256) __half g_h1Ta[32 * TILE_H], g_h1Tb[32 * TILE_H];
__device__ __align__(256) __half g_h1lin[BB * HH];             // for fc
__device__ __align__(256) __half g_fcwh[OUTD * HH];
__device__ __align__(256) float  g_bias0[G4], g_bias1[G4];
__device__ __align__(256) float  g_c0[BB * HH], g_c1[BB * HH];
__device__ unsigned g_barcnt;

// swizzled half-offset inside a 64x64 tile for (row, col8unit, elem)
__device__ __forceinline__ int swz_off(int row, int u, int e) {
    return row * 64 + ((u ^ (row & 7)) << 3) + e;
}

// ---------------- setup: pack + swizzle everything ----------------
__global__ void setup_kernel(const float* __restrict__ inputs,
                             const float* __restrict__ hiddens,
                             const float* __restrict__ cells,
                             const float* __restrict__ W_ih0,
                             const float* __restrict__ W_hh0,
                             const float* __restrict__ b_ih0,
                             const float* __restrict__ b_hh0,
                             const float* __restrict__ W_ih1,
                             const float* __restrict__ W_hh1,
                             const float* __restrict__ b_ih1,
                             const float* __restrict__ b_hh1,
                             const float* __restrict__ fc_w) {
    int i = blockIdx.x * blockDim.x + threadIdx.x;
    if (i == 0) g_barcnt = 0;

    const int S1 = NCTA * NT0 * 512;       // 2228224 vec8 units, W0 pack
    if (i < S1) {
        int bn = i / (NT0 * 512), r1 = i % (NT0 * 512);
        int T = r1 / 512, r2 = r1 & 511;
        int jj = r2 >> 3, u = r2 & 7;
        int R = (jj >> 4) * HH + bn * 16 + (jj & 15);
        __half tmp[8];
        if (T < NT0I) {
            #pragma unroll
            for (int e = 0; e < 8; e++) {
                int c = T * 64 + u * 8 + e;
                tmp[e] = __float2half(c < HIN ? W_ih0[(size_t)R * HIN + c] : 0.f);
            }
        } else {
            const float* s = W_hh0 + (size_t)R * HH + (T - NT0I) * 64 + u * 8;
            #pragma unroll
            for (int e = 0; e < 8; e++) tmp[e] = __float2half(s[e]);
        }
        size_t dst = ((size_t)(bn * NT0 + T) * 64 + jj) * 64 + ((u ^ (jj & 7)) << 3);
        *reinterpret_cast<uint4*>(g_W0p + dst) = *reinterpret_cast<uint4*>(tmp);
        return;
    }
    i -= S1;
    const int S2 = NCTA * NT1 * 512;       // 4194304, W1 pack
    if (i < S2) {
        int bn = i / (NT1 * 512), r1 = i % (NT1 * 512);
        int T = r1 / 512, r2 = r1 & 511;
        int jj = r2 >> 3, u = r2 & 7;
        int R = (jj >> 4) * HH + bn * 16 + (jj & 15);
        const float* s = (T < NT1I)
            ? W_ih1 + (size_t)R * HH + T * 64 + u * 8
            : W_hh1 + (size_t)R * HH + (T - NT1I) * 64 + u * 8;
        __half tmp[8];
        #pragma unroll
        for (int e = 0; e < 8; e++) tmp[e] = __float2half(s[e]);
        size_t dst = ((size_t)(bn * NT1 + T) * 64 + jj) * 64 + ((u ^ (jj & 7)) << 3);
        *reinterpret_cast<uint4*>(g_W1p + dst) = *reinterpret_cast<uint4*>(tmp);
        return;
    }
    i -= S2;
    const int S3 = 2 * 512;                // xT
    if (i < S3) {
        int kt = i / 512, r2 = i % 512;
        int r = r2 >> 3, u = r2 & 7;
        int j = kt * 64 + r;
        __half tmp[8];
        #pragma unroll
        for (int e = 0; e < 8; e++) {
            int b = u * 8 + e;
            tmp[e] = __float2half(j < HIN ? inputs[b * HIN + j] : 0.f);
        }
        *reinterpret_cast<uint4*>(g_xT + kt * TILE_H + swz_off(r, u, 0)) =
            *reinterpret_cast<uint4*>(tmp);
        return;
    }
    i -= S3;
    const int S4 = 32 * 512;               // h0Ta
    if (i < S4) {
        int kt = i / 512, r2 = i % 512;
        int r = r2 >> 3, u = r2 & 7;
        int j = kt * 64 + r;
        __half tmp[8];
        #pragma unroll
        for (int e = 0; e < 8; e++)
            tmp[e] = __float2half(hiddens[(size_t)(u * 8 + e) * HH + j]);
        *reinterpret_cast<uint4*>(g_h0Ta + kt * TILE_H + swz_off(r, u, 0)) =
            *reinterpret_cast<uint4*>(tmp);
        return;
    }
    i -= S4;
    if (i < S4) {                          // h1Ta
        int kt = i / 512, r2 = i % 512;
        int r = r2 >> 3, u = r2 & 7;
        int j = kt * 64 + r;
        __half tmp[8];
        #pragma unroll
        for (int e = 0; e < 8; e++)
            tmp[e] = __float2half(hiddens[(size_t)BB * HH + (size_t)(u * 8 + e) * HH + j]);
        *reinterpret_cast<uint4*>(g_h1Ta + kt * TILE_H + swz_off(r, u, 0)) =
            *reinterpret_cast<uint4*>(tmp);
        return;
    }
    i -= S4;
    if (i < G4) { g_bias0[i] = b_ih0[i] + b_hh0[i]; return; }
    i -= G4;
    if (i < G4) { g_bias1[i] = b_ih1[i] + b_hh1[i]; return; }
    i -= G4;
    const int S7 = OUTD * HH / 8;          // 16896, fcw
    if (i < S7) {
        float4 f0 = *reinterpret_cast<const float4*>(fc_w + (size_t)i * 8);
        float4 f1 = *reinterpret_cast<const float4*>(fc_w + (size_t)i * 8 + 4);
        uint4 u;
        *reinterpret_cast<__half2*>(&u.x) = __floats2half2_rn(f0.x, f0.y);
        *reinterpret_cast<__half2*>(&u.y) = __floats2half2_rn(f0.z, f0.w);
        *reinterpret_cast<__half2*>(&u.z) = __floats2half2_rn(f1.x, f1.y);
        *reinterpret_cast<__half2*>(&u.w) = __floats2half2_rn(f1.z, f1.w);
        reinterpret_cast<uint4*>(g_fcwh)[i] = u;
        return;
    }
    i -= S7;
    const int S8 = BB * HH / 4;            // 32768
    if (i < S8) {
        reinterpret_cast<float4*>(g_c0)[i] =
            reinterpret_cast<const float4*>(cells)[i];
        return;
    }
    i -= S8;
    if (i < S8) {
        reinterpret_cast<float4*>(g_c1)[i] =
            reinterpret_cast<const float4*>(cells + (size_t)BB * HH)[i];
        return;
    }
}

// ---------------- software grid barrier ----------------
__device__ __forceinline__ void grid_bar(unsigned target) {
    __syncthreads();
    if (threadIdx.x == 0) {
        __threadfence();
        atomicAdd(&g_barcnt, 1u);
        unsigned v;
        do {
            asm volatile("ld.acquire.gpu.u32 %0, [%1];" : "=r"(v)
                         : "l"(&g_barcnt) : "memory");
        } while (v < target);
    }
    __syncthreads();
}

// ---------------- mbarrier primitives ----------------
__device__ __forceinline__ void mbar_init(uint32_t bar, uint32_t cnt) {
    asm volatile("mbarrier.init.shared.b64 [%0], %1;" :: "r"(bar), "r"(cnt) : "memory");
}
__device__ __forceinline__ void mbar_expect_tx(uint32_t bar, uint32_t bytes) {
    asm volatile("mbarrier.arrive.expect_tx.shared.b64 _, [%0], %1;"
                 :: "r"(bar), "r"(bytes) : "memory");
}
__device__ __forceinline__ void bulk_g2s(uint32_t dst, const void* src,
                                         uint32_t bytes, uint32_t bar) {
    asm volatile("cp.async.bulk.shared::cluster.global.mbarrier::complete_tx::bytes "
                 "[%0], [%1], %2, [%3];"
                 :: "r"(dst), "l"(src), "r"(bytes), "r"(bar) : "memory");
}
__device__ __forceinline__ void mbar_wait(uint32_t bar, uint32_t parity) {
    asm volatile(
        "{\n\t.reg .pred P;\n"
        "W%=:\n\t"
        "mbarrier.try_wait.parity.acquire.cta.shared::cta.b64 P, [%0], %1, 0x989680;\n\t"
        "@P bra D%=;\n\t"
        "bra W%=;\n"
        "D%=:\n\t}"
        :: "r"(bar), "r"(parity) : "memory");
}

__device__ __forceinline__ void mma16816(float (&c)[4], uint32_t a0, uint32_t a1,
                                         uint32_t a2, uint32_t a3,
                                         uint32_t b0, uint32_t b1) {
    asm volatile(
        "mma.sync.aligned.m16n8k16.row.col.f32.f16.f16.f32 "
        "{%0,%1,%2,%3}, {%4,%5,%6,%7}, {%8,%9}, {%0,%1,%2,%3};\n"
        : "+f"(c[0]), "+f"(c[1]), "+f"(c[2]), "+f"(c[3])
        : "r"(a0), "r"(a1), "r"(a2), "r"(a3), "r"(b0), "r"(b1));
}

// ---------------- fused LSTM cell body ----------------
// 512 threads: warpgroup wg (0/1) owns k-half wg*32..wg*32+31 of every 64-k tile.
// smem stages: stage s at byte s*16384 (A 8KB | W 8KB); barriers at 98304.
template<bool WRITE_LIN>
__device__ __forceinline__ void cell_body(char* smc, uint32_t smb,
                                          int tbase, int NTI, int NT,
                                          const __half* __restrict__ A0,
                                          const __half* __restrict__ A1,
                                          const __half* __restrict__ Wp,
                                          const float* __restrict__ bias,
                                          float* __restrict__ c_state,
                                          __half* __restrict__ hT_out,
                                          __half* __restrict__ h_lin,
                                          int bn, int tid) {
    const int lane = tid & 31, warp = tid >> 5;
    const int wg = warp >> 3, wwarp = warp & 7;
    const int wm = wwarp & 3, wn = wwarp >> 2;
    const uint32_t barb = smb + NST * 16384;

    float acc[4][4];
    #pragma unroll
    for (int a = 0; a < 4; a++)
        #pragma unroll
        for (int b = 0; b < 4; b++) acc[a][b] = 0.f;

    auto issue = [&](int t) {
        int s = (tbase + t) % NST;
        uint32_t bar = barb + s * 8;
        mbar_expect_tx(bar, 16384);
        const __half* asrc = (t < NTI) ? A0 + (size_t)t * TILE_H
                                       : A1 + (size_t)(t - NTI) * TILE_H;
        bulk_g2s(smb + s * 16384, asrc, 8192, bar);
        bulk_g2s(smb + s * 16384 + 8192, Wp + (size_t)t * TILE_H, 8192, bar);
    };

    if (tid == 0) {
        #pragma unroll
        for (int p = 0; p < NST; p++) issue(p);
    }

    // per-lane constant addressing (A transposed [k][b], W [jj][k])
    const int q = lane >> 3;
    const int kbA = (q >> 1) * 8 + (lane & 7);
    const int mcol = wm * 16 + (q & 1) * 8;
    const int swzA = (((mcol >> 3) ^ (kbA & 7)) << 3);
    const int jjL = wn * 32 + (lane & 15);
    const int klane = lane >> 4;
    const int jmask = jjL & 7;

    for (int t = 0; t < NT; t++) {
        int tg = tbase + t;
        int s = tg % NST;
        mbar_wait(barb + s * 8, (tg / NST) & 1);
        uint32_t abuf = smb + s * 16384;
        uint32_t wbuf = abuf + 8192;
        #pragma unroll
        for (int kh = 0; kh < 2; kh++) {
            int kk = wg * 32 + kh * 16;
            uint32_t aaddr = abuf + ((kk + kbA) << 7) + (swzA << 1);
            uint32_t waddr1 = wbuf + (jjL << 7)
                            + ((((klane + (kk >> 3)) ^ jmask) << 3) << 1);
            uint32_t waddr2 = waddr1 + (16 << 7);
            uint32_t a0, a1, a2, a3, p0, p1, p2, p3, q0, q1, q2, q3;
            asm volatile("ldmatrix.sync.aligned.m8n8.x4.trans.shared.b16 "
                         "{%0,%1,%2,%3}, [%4];\n"
                         : "=r"(a0), "=r"(a1), "=r"(a2), "=r"(a3) : "r"(aaddr));
            asm volatile("ldmatrix.sync.aligned.m8n8.x4.shared.b16 "
                         "{%0,%1,%2,%3}, [%4];\n"
                         : "=r"(p0), "=r"(p1), "=r"(p2), "=r"(p3) : "r"(waddr1));
            asm volatile("ldmatrix.sync.aligned.m8n8.x4.shared.b16 "
                         "{%0,%1,%2,%3}, [%4];\n"
                         : "=r"(q0), "=r"(q1), "=r"(q2), "=r"(q3) : "r"(waddr2));
            mma16816(acc[0], a0, a1, a2, a3, p0, p2);
            mma16816(acc[1], a0, a1, a2, a3, p1, p3);
            mma16816(acc[2], a0, a1, a2, a3, q0, q2);
            mma16816(acc[3], a0, a1, a2, a3, q1, q3);
        }
        __syncthreads();
        if (tid == 0 && t + NST < NT) issue(t + NST);
    }

    // epilogue: merge the two warpgroups' k-partials in smem, then elementwise
    float* Gs = reinterpret_cast<float*>(smc);
    const int row = wm * 16 + (lane >> 2);
    const int col0 = wn * 32 + (lane & 3) * 2;
    if (wg == 0) {
        #pragma unroll
        for (int nt = 0; nt < 4; nt++) {
            int col = col0 + nt * 8;
            Gs[row * 68 + col]           = acc[nt][0];
            Gs[row * 68 + col + 1]       = acc[nt][1];
            Gs[(row + 8) * 68 + col]     = acc[nt][2];
            Gs[(row + 8) * 68 + col + 1] = acc[nt][3];
        }
    }
    __syncthreads();
    if (wg == 1) {
        #pragma unroll
        for (int nt = 0; nt < 4; nt++) {
            int col = col0 + nt * 8;
            Gs[row * 68 + col]           += acc[nt][0];
            Gs[row * 68 + col + 1]       += acc[nt][1];
            Gs[(row + 8) * 68 + col]     += acc[nt][2];
            Gs[(row + 8) * 68 + col + 1] += acc[nt][3];
        }
    }
    __syncthreads();

    #pragma unroll
    for (int it = 0; it < 2; it++) {
        int sidx = tid + it * NTHR;
        int b = sidx >> 4, c = sidx & 15;
        int hcol = bn * 16 + c;
        float vi = Gs[b * 68 + c]      + bias[hcol];
        float vf = Gs[b * 68 + 16 + c] + bias[HH + hcol];
        float vg = Gs[b * 68 + 32 + c] + bias[2 * HH + hcol];
        float vo = Gs[b * 68 + 48 + c] + bias[3 * HH + hcol];
        float ii = 1.f / (1.f + __expf(-vi));
        float ff = 1.f / (1.f + __expf(-vf));
        float gg = tanhf(vg);
        float oo = 1.f / (1.f + __expf(-vo));
        int idx = b * HH + hcol;
        float c2 = ff * c_state[idx] + ii * gg;
        c_state[idx] = c2;
        __half hv = __float2half(oo * tanhf(c2));
        int kt = hcol >> 6, r = hcol & 63;
        hT_out[kt * TILE_H + swz_off(r, b >> 3, b & 7)] = hv;
        if (WRITE_LIN) h_lin[idx] = hv;
    }
    __syncthreads();
}

// ---------------- fc phase ----------------
__device__ __forceinline__ void fc_phase(const __half* __restrict__ h1,
                                         const __half* __restrict__ fcw,
                                         const float* __restrict__ fc_b,
                                         float* __restrict__ out,
                                         int t, int tid, int bid) {
    int gw = bid * 16 + (tid >> 5);
    int lane = tid & 31;
    for (int task = gw; task < OUTD * BB; task += NCTA * 16) {
        int j = task % OUTD, b = task / OUTD;
        const uint4* w4 = reinterpret_cast<const uint4*>(fcw + (size_t)j * HH);
        const uint4* h4 = reinterpret_cast<const uint4*>(h1 + (size_t)b * HH);
        float s = 0.f;
        #pragma unroll
        for (int it = 0; it < 8; it++) {
            int k = lane + it * 32;
            uint4 wu = w4[k], hu = h4[k];
            const __half2* wp = reinterpret_cast<const __half2*>(&wu);
            const __half2* hp = reinterpret_cast<const __half2*>(&hu);
            #pragma unroll
            for (int e = 0; e < 4; e++) {
                float2 wf = __half22float2(wp[e]);
                float2 hf = __half22float2(hp[e]);
                s += wf.x * hf.x + wf.y * hf.y;
            }
        }
        #pragma unroll
        for (int o = 16; o; o >>= 1) s += __shfl_xor_sync(0xffffffffu, s, o);
        if (lane == 0) {
            float v = s + fc_b[j];
            v = fminf(fmaxf(v, -1.f), 1.f);
            out[(size_t)b * (TT * OUTD) + t * OUTD + j] = v;
            int kt = j >> 6, r = j & 63;
            g_xT[kt * TILE_H + swz_off(r, b >> 3, b & 7)] = __float2half(v);
        }
    }
}

// ---------------- one full step ----------------
__global__ void __launch_bounds__(NTHR, 1)
step_kernel(const __half* __restrict__ h0T_in, __half* __restrict__ h0T_out,
            const __half* __restrict__ h1T_in, __half* __restrict__ h1T_out,
            const float* __restrict__ fc_b, float* __restrict__ out, int t) {
    extern __shared__ char smc[];
    uint32_t smb = (uint32_t)__cvta_generic_to_shared(smc);
    int tid = threadIdx.x, bn = blockIdx.x;

    if (tid == 0) {
        #pragma unroll
        for (int s = 0; s < NST; s++) mbar_init(smb + NST * 16384 + s * 8, 1);
    }
    __syncthreads();

    cell_body<false>(smc, smb, 0, NT0I, NT0,
                     g_xT, h0T_in, g_W0p + (size_t)bn * NT0 * TILE_H,
                     g_bias0, g_c0, h0T_out, nullptr, bn, tid);
    grid_bar((unsigned)(2 * t + 1) * NCTA);
    cell_body<true>(smc, smb, NT0, NT1I, NT1,
                    h0T_out, h1T_in, g_W1p + (size_t)bn * NT1 * TILE_H,
                    g_bias1, g_c1, h1T_out, g_h1lin, bn, tid);
    grid_bar((unsigned)(2 * t + 2) * NCTA);
    fc_phase(g_h1lin, g_fcwh, fc_b, out, t, tid, bn);
}

// ---------------- launch ----------------
extern "C" void kernel_launch(void* const* d_in, const int* in_sizes, int n_in,
                              void* d_out, int out_size) {
    (void)in_sizes; (void)n_in; (void)out_size;
    const float* inputs  = (const float*)d_in[0];
    const float* hiddens = (const float*)d_in[1];
    const float* cells   = (const float*)d_in[2];
    const float* W_ih0   = (const float*)d_in[3];
    const float* W_hh0   = (const float*)d_in[4];
    const float* b_ih0   = (const float*)d_in[5];
    const float* b_hh0   = (const float*)d_in[6];
    const float* W_ih1   = (const float*)d_in[7];
    const float* W_hh1   = (const float*)d_in[8];
    const float* b_ih1   = (const float*)d_in[9];
    const float* b_hh1   = (const float*)d_in[10];
    const float* fc_w    = (const float*)d_in[11];
    const float* fc_b    = (const float*)d_in[12];
    float* out = (float*)d_out;

    __half *p_h0a, *p_h0b, *p_h1a, *p_h1b;
    cudaGetSymbolAddress((void**)&p_h0a, g_h0Ta);
    cudaGetSymbolAddress((void**)&p_h0b, g_h0Tb);
    cudaGetSymbolAddress((void**)&p_h1a, g_h1Ta);
    cudaGetSymbolAddress((void**)&p_h1b, g_h1Tb);

    static const int SMEM_BYTES = NST * 16384 + 1024;
    cudaFuncSetAttribute(step_kernel,
                         cudaFuncAttributeMaxDynamicSharedMemorySize, SMEM_BYTES);

    const long SETUP_N = 6555136;
    setup_kernel<<<(int)((SETUP_N + 255) / 256), 256>>>(
        inputs, hiddens, cells, W_ih0, W_hh0, b_ih0, b_hh0,
        W_ih1, W_hh1, b_ih1, b_hh1, fc_w);

    for (int t = 0; t < TT; t++) {
        __half* h0_in  = (t & 1) ? p_h0b : p_h0a;
        __half* h0_out = (t & 1) ? p_h0a : p_h0b;
        __half* h1_in  = (t & 1) ? p_h1b : p_h1a;
        __half* h1_out = (t & 1) ? p_h1a : p_h1b;
        step_kernel<<<NCTA, NTHR, SMEM_BYTES>>>(h0_in, h0_out, h1_in, h1_out,
                                                fc_b, out, t);
    }
}

// round 8
// speedup vs baseline: 4.9155x; 1.2537x over previous
#include <cuda_runtime.h>
#include <cuda_fp16.h>
#include <cstdint>
#include <math.h>

#define BB   64
#define HH   2048
#define HIN  66
#define TT   25
#define OUTD 66
#define G4   8192
#define NCTA 128
#define NTHR 544        // 16 compute warps + 1 producer warp
#define NST  12         // pipeline stages
#define STAGE 16384     // bytes per stage: 8KB act + 8KB weight
#define GS_OFF (NST * STAGE)          // 196608: epilogue float scratch
#define BAR_OFF (GS_OFF + 17408)      // 214016: mbarriers
#define SMEM_BYTES (BAR_OFF + 256)    // 214272
#define NT0I 2
#define NT0  34
#define NT1I 32
#define NT1  64
#define TILE_H 4096     // halves per 64x64 tile

// ---------------- device scratch ----------------
__device__ __align__(256) __half g_W0p[NCTA * NT0 * TILE_H];   // 34 MB
__device__ __align__(256) __half g_W1p[NCTA * NT1 * TILE_H];   // 64 MB
__device__ __align__(256) __half g_xT[2 * TILE_H];
__device__ __align__(256) __half g_h0Ta[32 * TILE_H], g_h0Tb[32 * TILE_H];
__device__ __align__(256) __half g_h1Ta[32 * TILE_H], g_h1Tb[32 * TILE_H];
__device__ __align__(256) __half g_h1lin[BB * HH];
__device__ __align__(256) __half g_fcwh[OUTD * HH];
__device__ __align__(256) float  g_bias0[G4], g_bias1[G4];
__device__ __align__(256) float  g_c0[BB * HH], g_c1[BB * HH];
__device__ unsigned g_barcnt;

__device__ __forceinline__ int swz_off(int row, int u, int e) {
    return row * 64 + ((u ^ (row & 7)) << 3) + e;
}

// ---------------- setup (unchanged from R7) ----------------
__global__ void setup_kernel(const float* __restrict__ inputs,
                             const float* __restrict__ hiddens,
                             const float* __restrict__ cells,
                             const float* __restrict__ W_ih0,
                             const float* __restrict__ W_hh0,
                             const float* __restrict__ b_ih0,
                             const float* __restrict__ b_hh0,
                             const float* __restrict__ W_ih1,
                             const float* __restrict__ W_hh1,
                             const float* __restrict__ b_ih1,
                             const float* __restrict__ b_hh1,
                             const float* __restrict__ fc_w) {
    int i = blockIdx.x * blockDim.x + threadIdx.x;
    if (i == 0) g_barcnt = 0;

    const int S1 = NCTA * NT0 * 512;
    if (i < S1) {
        int bn = i / (NT0 * 512), r1 = i % (NT0 * 512);
        int T = r1 / 512, r2 = r1 & 511;
        int jj = r2 >> 3, u = r2 & 7;
        int R = (jj >> 4) * HH + bn * 16 + (jj & 15);
        __half tmp[8];
        if (T < NT0I) {
            #pragma unroll
            for (int e = 0; e < 8; e++) {
                int c = T * 64 + u * 8 + e;
                tmp[e] = __float2half(c < HIN ? W_ih0[(size_t)R * HIN + c] : 0.f);
            }
        } else {
            const float* s = W_hh0 + (size_t)R * HH + (T - NT0I) * 64 + u * 8;
            #pragma unroll
            for (int e = 0; e < 8; e++) tmp[e] = __float2half(s[e]);
        }
        size_t dst = ((size_t)(bn * NT0 + T) * 64 + jj) * 64 + ((u ^ (jj & 7)) << 3);
        *reinterpret_cast<uint4*>(g_W0p + dst) = *reinterpret_cast<uint4*>(tmp);
        return;
    }
    i -= S1;
    const int S2 = NCTA * NT1 * 512;
    if (i < S2) {
        int bn = i / (NT1 * 512), r1 = i % (NT1 * 512);
        int T = r1 / 512, r2 = r1 & 511;
        int jj = r2 >> 3, u = r2 & 7;
        int R = (jj >> 4) * HH + bn * 16 + (jj & 15);
        const float* s = (T < NT1I)
            ? W_ih1 + (size_t)R * HH + T * 64 + u * 8
            : W_hh1 + (size_t)R * HH + (T - NT1I) * 64 + u * 8;
        __half tmp[8];
        #pragma unroll
        for (int e = 0; e < 8; e++) tmp[e] = __float2half(s[e]);
        size_t dst = ((size_t)(bn * NT1 + T) * 64 + jj) * 64 + ((u ^ (jj & 7)) << 3);
        *reinterpret_cast<uint4*>(g_W1p + dst) = *reinterpret_cast<uint4*>(tmp);
        return;
    }
    i -= S2;
    const int S3 = 2 * 512;
    if (i < S3) {
        int kt = i / 512, r2 = i % 512;
        int r = r2 >> 3, u = r2 & 7;
        int j = kt * 64 + r;
        __half tmp[8];
        #pragma unroll
        for (int e = 0; e < 8; e++) {
            int b = u * 8 + e;
            tmp[e] = __float2half(j < HIN ? inputs[b * HIN + j] : 0.f);
        }
        *reinterpret_cast<uint4*>(g_xT + kt * TILE_H + swz_off(r, u, 0)) =
            *reinterpret_cast<uint4*>(tmp);
        return;
    }
    i -= S3;
    const int S4 = 32 * 512;
    if (i < S4) {
        int kt = i / 512, r2 = i % 512;
        int r = r2 >> 3, u = r2 & 7;
        int j = kt * 64 + r;
        __half tmp[8];
        #pragma unroll
        for (int e = 0; e < 8; e++)
            tmp[e] = __float2half(hiddens[(size_t)(u * 8 + e) * HH + j]);
        *reinterpret_cast<uint4*>(g_h0Ta + kt * TILE_H + swz_off(r, u, 0)) =
            *reinterpret_cast<uint4*>(tmp);
        return;
    }
    i -= S4;
    if (i < S4) {
        int kt = i / 512, r2 = i % 512;
        int r = r2 >> 3, u = r2 & 7;
        int j = kt * 64 + r;
        __half tmp[8];
        #pragma unroll
        for (int e = 0; e < 8; e++)
            tmp[e] = __float2half(hiddens[(size_t)BB * HH + (size_t)(u * 8 + e) * HH + j]);
        *reinterpret_cast<uint4*>(g_h1Ta + kt * TILE_H + swz_off(r, u, 0)) =
            *reinterpret_cast<uint4*>(tmp);
        return;
    }
    i -= S4;
    if (i < G4) { g_bias0[i] = b_ih0[i] + b_hh0[i]; return; }
    i -= G4;
    if (i < G4) { g_bias1[i] = b_ih1[i] + b_hh1[i]; return; }
    i -= G4;
    const int S7 = OUTD * HH / 8;
    if (i < S7) {
        float4 f0 = *reinterpret_cast<const float4*>(fc_w + (size_t)i * 8);
        float4 f1 = *reinterpret_cast<const float4*>(fc_w + (size_t)i * 8 + 4);
        uint4 u;
        *reinterpret_cast<__half2*>(&u.x) = __floats2half2_rn(f0.x, f0.y);
        *reinterpret_cast<__half2*>(&u.y) = __floats2half2_rn(f0.z, f0.w);
        *reinterpret_cast<__half2*>(&u.z) = __floats2half2_rn(f1.x, f1.y);
        *reinterpret_cast<__half2*>(&u.w) = __floats2half2_rn(f1.z, f1.w);
        reinterpret_cast<uint4*>(g_fcwh)[i] = u;
        return;
    }
    i -= S7;
    const int S8 = BB * HH / 4;
    if (i < S8) {
        reinterpret_cast<float4*>(g_c0)[i] =
            reinterpret_cast<const float4*>(cells)[i];
        return;
    }
    i -= S8;
    if (i < S8) {
        reinterpret_cast<float4*>(g_c1)[i] =
            reinterpret_cast<const float4*>(cells + (size_t)BB * HH)[i];
        return;
    }
}

// ---------------- grid barrier ----------------
__device__ __forceinline__ void grid_bar(unsigned target) {
    __syncthreads();
    if (threadIdx.x == 0) {
        __threadfence();
        atomicAdd(&g_barcnt, 1u);
        unsigned v;
        do {
            asm volatile("ld.acquire.gpu.u32 %0, [%1];" : "=r"(v)
                         : "l"(&g_barcnt) : "memory");
        } while (v < target);
    }
    __syncthreads();
}

// ---------------- mbarrier primitives ----------------
__device__ __forceinline__ void mbar_init(uint32_t bar, uint32_t cnt) {
    asm volatile("mbarrier.init.shared.b64 [%0], %1;" :: "r"(bar), "r"(cnt) : "memory");
}
__device__ __forceinline__ void mbar_expect_tx(uint32_t bar, uint32_t bytes) {
    asm volatile("mbarrier.arrive.expect_tx.shared.b64 _, [%0], %1;"
                 :: "r"(bar), "r"(bytes) : "memory");
}
__device__ __forceinline__ void mbar_arrive(uint32_t bar) {
    asm volatile("mbarrier.arrive.shared.b64 _, [%0];" :: "r"(bar) : "memory");
}
__device__ __forceinline__ void bulk_g2s(uint32_t dst, const void* src,
                                         uint32_t bytes, uint32_t bar) {
    asm volatile("cp.async.bulk.shared::cluster.global.mbarrier::complete_tx::bytes "
                 "[%0], [%1], %2, [%3];"
                 :: "r"(dst), "l"(src), "r"(bytes), "r"(bar) : "memory");
}
// weight copies: L2 evict_last hint (weights ~100MB, want them resident)
__device__ __forceinline__ void bulk_g2s_el(uint32_t dst, const void* src,
                                            uint32_t bytes, uint32_t bar) {
    uint64_t pol;
    asm volatile("createpolicy.fractional.L2::evict_last.b64 %0;" : "=l"(pol));
    asm volatile("cp.async.bulk.shared::cluster.global.mbarrier::complete_tx::bytes.L2::cache_hint "
                 "[%0], [%1], %2, [%3], %4;"
                 :: "r"(dst), "l"(src), "r"(bytes), "r"(bar), "l"(pol) : "memory");
}
__device__ __forceinline__ void mbar_wait(uint32_t bar, uint32_t parity) {
    asm volatile(
        "{\n\t.reg .pred P;\n"
        "W%=:\n\t"
        "mbarrier.try_wait.parity.acquire.cta.shared::cta.b64 P, [%0], %1, 0x989680;\n\t"
        "@P bra D%=;\n\t"
        "bra W%=;\n"
        "D%=:\n\t}"
        :: "r"(bar), "r"(parity) : "memory");
}

__device__ __forceinline__ void mma16816(float (&c)[4], uint32_t a0, uint32_t a1,
                                         uint32_t a2, uint32_t a3,
                                         uint32_t b0, uint32_t b1) {
    asm volatile(
        "mma.sync.aligned.m16n8k16.row.col.f32.f16.f16.f32 "
        "{%0,%1,%2,%3}, {%4,%5,%6,%7}, {%8,%9}, {%0,%1,%2,%3};\n"
        : "+f"(c[0]), "+f"(c[1]), "+f"(c[2]), "+f"(c[3])
        : "r"(a0), "r"(a1), "r"(a2), "r"(a3), "r"(b0), "r"(b1));
}

// ---------------- fused LSTM cell body: warp-specialized free-running ----------
// warps 0-15 compute (wg = warp>>3 owns k-half), warp 16 produces.
template<bool WRITE_LIN>
__device__ __forceinline__ void cell_body(char* smc, uint32_t smb,
                                          int tbase, int NTI, int NT,
                                          const __half* __restrict__ A0,
                                          const __half* __restrict__ A1,
                                          const __half* __restrict__ Wp,
                                          const float* __restrict__ bias,
                                          float* __restrict__ c_state,
                                          __half* __restrict__ hT_out,
                                          __half* __restrict__ h_lin,
                                          int bn, int tid) {
    const int lane = tid & 31, warp = tid >> 5;
    const uint32_t fullb  = smb + BAR_OFF;
    const uint32_t emptyb = smb + BAR_OFF + 128;

    float acc[4][4];
    #pragma unroll
    for (int a = 0; a < 4; a++)
        #pragma unroll
        for (int b = 0; b < 4; b++) acc[a][b] = 0.f;

    if (warp == 16) {
        // ---- producer warp: free-running bulk-copy issue ----
        if (lane == 0) {
            for (int t = 0; t < NT; t++) {
                int tg = tbase + t, s = tg % NST;
                if (tg >= NST) mbar_wait(emptyb + s * 8, ((tg / NST) - 1) & 1);
                uint32_t bar = fullb + s * 8;
                mbar_expect_tx(bar, STAGE);
                const __half* asrc = (t < NTI) ? A0 + (size_t)t * TILE_H
                                               : A1 + (size_t)(t - NTI) * TILE_H;
                bulk_g2s(smb + s * STAGE, asrc, 8192, bar);
                bulk_g2s_el(smb + s * STAGE + 8192, Wp + (size_t)t * TILE_H,
                            8192, bar);
            }
        }
    } else {
        // ---- consumer warps: free-running, no __syncthreads in loop ----
        const int wg = warp >> 3, wwarp = warp & 7;
        const int wm = wwarp & 3, wn = wwarp >> 2;
        const int q = lane >> 3;
        const int kbA = (q >> 1) * 8 + (lane & 7);
        const int mcol = wm * 16 + (q & 1) * 8;
        const int swzA = (((mcol >> 3) ^ (kbA & 7)) << 3);
        const int jjL = wn * 32 + (lane & 15);
        const int klane = lane >> 4;
        const int jmask = jjL & 7;

        for (int t = 0; t < NT; t++) {
            int tg = tbase + t;
            int s = tg % NST;
            mbar_wait(fullb + s * 8, (tg / NST) & 1);
            uint32_t abuf = smb + s * STAGE;
            uint32_t wbuf = abuf + 8192;
            #pragma unroll
            for (int kh = 0; kh < 2; kh++) {
                int kk = wg * 32 + kh * 16;
                uint32_t aaddr = abuf + ((kk + kbA) << 7) + (swzA << 1);
                uint32_t waddr1 = wbuf + (jjL << 7)
                                + ((((klane + (kk >> 3)) ^ jmask) << 3) << 1);
                uint32_t waddr2 = waddr1 + (16 << 7);
                uint32_t a0, a1, a2, a3, p0, p1, p2, p3, q0, q1, q2, q3;
                asm volatile("ldmatrix.sync.aligned.m8n8.x4.trans.shared.b16 "
                             "{%0,%1,%2,%3}, [%4];\n"
                             : "=r"(a0), "=r"(a1), "=r"(a2), "=r"(a3) : "r"(aaddr));
                asm volatile("ldmatrix.sync.aligned.m8n8.x4.shared.b16 "
                             "{%0,%1,%2,%3}, [%4];\n"
                             : "=r"(p0), "=r"(p1), "=r"(p2), "=r"(p3) : "r"(waddr1));
                asm volatile("ldmatrix.sync.aligned.m8n8.x4.shared.b16 "
                             "{%0,%1,%2,%3}, [%4];\n"
                             : "=r"(q0), "=r"(q1), "=r"(q2), "=r"(q3) : "r"(waddr2));
                mma16816(acc[0], a0, a1, a2, a3, p0, p2);
                mma16816(acc[1], a0, a1, a2, a3, p1, p3);
                mma16816(acc[2], a0, a1, a2, a3, q0, q2);
                mma16816(acc[3], a0, a1, a2, a3, q1, q3);
            }
            if (lane == 0) mbar_arrive(emptyb + s * 8);
        }
    }

    // ---- epilogue: merge split-k partials, elementwise LSTM ----
    float* Gs = reinterpret_cast<float*>(smc + GS_OFF);
    const int wwarp = warp & 7;
    const int wm = wwarp & 3, wn = wwarp >> 2;
    const int row = wm * 16 + (lane >> 2);
    const int col0 = wn * 32 + (lane & 3) * 2;
    if (warp < 8) {                      // wg 0 stores
        #pragma unroll
        for (int nt = 0; nt < 4; nt++) {
            int col = col0 + nt * 8;
            Gs[row * 68 + col]           = acc[nt][0];
            Gs[row * 68 + col + 1]       = acc[nt][1];
            Gs[(row + 8) * 68 + col]     = acc[nt][2];
            Gs[(row + 8) * 68 + col + 1] = acc[nt][3];
        }
    }
    __syncthreads();
    if (warp >= 8 && warp < 16) {        // wg 1 accumulates
        #pragma unroll
        for (int nt = 0; nt < 4; nt++) {
            int col = col0 + nt * 8;
            Gs[row * 68 + col]           += acc[nt][0];
            Gs[row * 68 + col + 1]       += acc[nt][1];
            Gs[(row + 8) * 68 + col]     += acc[nt][2];
            Gs[(row + 8) * 68 + col + 1] += acc[nt][3];
        }
    }
    __syncthreads();
    if (tid < 512) {
        #pragma unroll
        for (int it = 0; it < 2; it++) {
            int sidx = tid + it * 512;
            int b = sidx >> 4, c = sidx & 15;
            int hcol = bn * 16 + c;
            float vi = Gs[b * 68 + c]      + bias[hcol];
            float vf = Gs[b * 68 + 16 + c] + bias[HH + hcol];
            float vg = Gs[b * 68 + 32 + c] + bias[2 * HH + hcol];
            float vo = Gs[b * 68 + 48 + c] + bias[3 * HH + hcol];
            float ii = 1.f / (1.f + __expf(-vi));
            float ff = 1.f / (1.f + __expf(-vf));
            float gg = tanhf(vg);
            float oo = 1.f / (1.f + __expf(-vo));
            int idx = b * HH + hcol;
            float c2 = ff * c_state[idx] + ii * gg;
            c_state[idx] = c2;
            __half hv = __float2half(oo * tanhf(c2));
            int kt = hcol >> 6, r = hcol & 63;
            hT_out[kt * TILE_H + swz_off(r, b >> 3, b & 7)] = hv;
            if (WRITE_LIN) h_lin[idx] = hv;
        }
    }
    __syncthreads();
}

// ---------------- fc phase ----------------
__device__ __forceinline__ void fc_phase(const __half* __restrict__ h1,
                                         const __half* __restrict__ fcw,
                                         const float* __restrict__ fc_b,
                                         float* __restrict__ out,
                                         int t, int tid, int bid) {
    int warp = tid >> 5;
    if (warp >= 16) return;
    int gw = bid * 16 + warp;
    int lane = tid & 31;
    for (int task = gw; task < OUTD * BB; task += NCTA * 16) {
        int j = task % OUTD, b = task / OUTD;
        const uint4* w4 = reinterpret_cast<const uint4*>(fcw + (size_t)j * HH);
        const uint4* h4 = reinterpret_cast<const uint4*>(h1 + (size_t)b * HH);
        float s = 0.f;
        #pragma unroll
        for (int it = 0; it < 8; it++) {
            int k = lane + it * 32;
            uint4 wu = w4[k], hu = h4[k];
            const __half2* wp = reinterpret_cast<const __half2*>(&wu);
            const __half2* hp = reinterpret_cast<const __half2*>(&hu);
            #pragma unroll
            for (int e = 0; e < 4; e++) {
                float2 wf = __half22float2(wp[e]);
                float2 hf = __half22float2(hp[e]);
                s += wf.x * hf.x + wf.y * hf.y;
            }
        }
        #pragma unroll
        for (int o = 16; o; o >>= 1) s += __shfl_xor_sync(0xffffffffu, s, o);
        if (lane == 0) {
            float v = s + fc_b[j];
            v = fminf(fmaxf(v, -1.f), 1.f);
            out[(size_t)b * (TT * OUTD) + t * OUTD + j] = v;
            int kt = j >> 6, r = j & 63;
            g_xT[kt * TILE_H + swz_off(r, b >> 3, b & 7)] = __float2half(v);
        }
    }
}

// ---------------- one full step ----------------
__global__ void __launch_bounds__(NTHR, 1)
step_kernel(const __half* __restrict__ h0T_in, __half* __restrict__ h0T_out,
            const __half* __restrict__ h1T_in, __half* __restrict__ h1T_out,
            const float* __restrict__ fc_b, float* __restrict__ out, int t) {
    extern __shared__ char smc[];
    uint32_t smb = (uint32_t)__cvta_generic_to_shared(smc);
    int tid = threadIdx.x, bn = blockIdx.x;

    if (tid == 0) {
        #pragma unroll
        for (int s = 0; s < NST; s++) {
            mbar_init(smb + BAR_OFF + s * 8, 1);          // full (tx-based)
            mbar_init(smb + BAR_OFF + 128 + s * 8, 16);   // empty (16 warps)
        }
    }
    __syncthreads();

    cell_body<false>(smc, smb, 0, NT0I, NT0,
                     g_xT, h0T_in, g_W0p + (size_t)bn * NT0 * TILE_H,
                     g_bias0, g_c0, h0T_out, nullptr, bn, tid);
    grid_bar((unsigned)(2 * t + 1) * NCTA);
    cell_body<true>(smc, smb, NT0, NT1I, NT1,
                    h0T_out, h1T_in, g_W1p + (size_t)bn * NT1 * TILE_H,
                    g_bias1, g_c1, h1T_out, g_h1lin, bn, tid);
    grid_bar((unsigned)(2 * t + 2) * NCTA);
    fc_phase(g_h1lin, g_fcwh, fc_b, out, t, tid, bn);
}

// ---------------- launch ----------------
extern "C" void kernel_launch(void* const* d_in, const int* in_sizes, int n_in,
                              void* d_out, int out_size) {
    (void)in_sizes; (void)n_in; (void)out_size;
    const float* inputs  = (const float*)d_in[0];
    const float* hiddens = (const float*)d_in[1];
    const float* cells   = (const float*)d_in[2];
    const float* W_ih0   = (const float*)d_in[3];
    const float* W_hh0   = (const float*)d_in[4];
    const float* b_ih0   = (const float*)d_in[5];
    const float* b_hh0   = (const float*)d_in[6];
    const float* W_ih1   = (const float*)d_in[7];
    const float* W_hh1   = (const float*)d_in[8];
    const float* b_ih1   = (const float*)d_in[9];
    const float* b_hh1   = (const float*)d_in[10];
    const float* fc_w    = (const float*)d_in[11];
    const float* fc_b    = (const float*)d_in[12];
    float* out = (float*)d_out;

    __half *p_h0a, *p_h0b, *p_h1a, *p_h1b;
    cudaGetSymbolAddress((void**)&p_h0a, g_h0Ta);
    cudaGetSymbolAddress((void**)&p_h0b, g_h0Tb);
    cudaGetSymbolAddress((void**)&p_h1a, g_h1Ta);
    cudaGetSymbolAddress((void**)&p_h1b, g_h1Tb);

    cudaFuncSetAttribute(step_kernel,
                         cudaFuncAttributeMaxDynamicSharedMemorySize, SMEM_BYTES);

    const long SETUP_N = 6555136;
    setup_kernel<<<(int)((SETUP_N + 255) / 256), 256>>>(
        inputs, hiddens, cells, W_ih0, W_hh0, b_ih0, b_hh0,
        W_ih1, W_hh1, b_ih1, b_hh1, fc_w);

    for (int t = 0; t < TT; t++) {
        __half* h0_in  = (t & 1) ? p_h0b : p_h0a;
        __half* h0_out = (t & 1) ? p_h0a : p_h0b;
        __half* h1_in  = (t & 1) ? p_h1b : p_h1a;
        __half* h1_out = (t & 1) ? p_h1a : p_h1b;
        step_kernel<<<NCTA, NTHR, SMEM_BYTES>>>(h0_in, h0_out, h1_in, h1_out,
                                                fc_b, out, t);
    }
}

// round 9
// speedup vs baseline: 5.2855x; 1.0753x over previous
#include <cuda_runtime.h>
#include <cuda_fp16.h>
#include <cstdint>
#include <math.h>

#define BB   64
#define HH   2048
#define HIN  66
#define TT   25
#define OUTD 66
#define G4   8192
#define NCTA 128
#define NTHR 544        // 16 consumer warps + 1 producer warp
#define NST  12
#define STAGE 16384     // 8KB act + 8KB weight
#define GS_OFF (NST * STAGE)
#define BAR_OFF (GS_OFF + 17408)
#define SMEM_BYTES (BAR_OFF + 256)
#define NT0I 2
#define NT0  34         // cell0 tiles (tg 0..33)
#define NT1  64         // cell1 tiles (tg 34..97); first 32 hh, last 32 ih
#define TILE_H 4096

// ---------------- device scratch ----------------
__device__ __align__(256) __half g_W0p[NCTA * NT0 * TILE_H];
__device__ __align__(256) __half g_W1p[NCTA * NT1 * TILE_H];
__device__ __align__(256) __half g_xT[2 * TILE_H];
__device__ __align__(256) __half g_h0Ta[32 * TILE_H], g_h0Tb[32 * TILE_H];
__device__ __align__(256) __half g_h1Ta[32 * TILE_H], g_h1Tb[32 * TILE_H];
__device__ __align__(256) __half g_h1lin[BB * HH];
__device__ __align__(256) __half g_fcwh[OUTD * HH];
__device__ __align__(256) float  g_bias0[G4], g_bias1[G4];
__device__ __align__(256) float  g_c0[BB * HH], g_c1[BB * HH];
__device__ unsigned g_barcnt;

__device__ __forceinline__ int swz_off(int row, int u, int e) {
    return row * 64 + ((u ^ (row & 7)) << 3) + e;
}

// ---------------- setup (W1 packed hh-first) ----------------
__global__ void setup_kernel(const float* __restrict__ inputs,
                             const float* __restrict__ hiddens,
                             const float* __restrict__ cells,
                             const float* __restrict__ W_ih0,
                             const float* __restrict__ W_hh0,
                             const float* __restrict__ b_ih0,
                             const float* __restrict__ b_hh0,
                             const float* __restrict__ W_ih1,
                             const float* __restrict__ W_hh1,
                             const float* __restrict__ b_ih1,
                             const float* __restrict__ b_hh1,
                             const float* __restrict__ fc_w) {
    int i = blockIdx.x * blockDim.x + threadIdx.x;
    if (i == 0) g_barcnt = 0;

    const int S1 = NCTA * NT0 * 512;
    if (i < S1) {
        int bn = i / (NT0 * 512), r1 = i % (NT0 * 512);
        int T = r1 / 512, r2 = r1 & 511;
        int jj = r2 >> 3, u = r2 & 7;
        int R = (jj >> 4) * HH + bn * 16 + (jj & 15);
        __half tmp[8];
        if (T < NT0I) {
            #pragma unroll
            for (int e = 0; e < 8; e++) {
                int c = T * 64 + u * 8 + e;
                tmp[e] = __float2half(c < HIN ? W_ih0[(size_t)R * HIN + c] : 0.f);
            }
        } else {
            const float* s = W_hh0 + (size_t)R * HH + (T - NT0I) * 64 + u * 8;
            #pragma unroll
            for (int e = 0; e < 8; e++) tmp[e] = __float2half(s[e]);
        }
        size_t dst = ((size_t)(bn * NT0 + T) * 64 + jj) * 64 + ((u ^ (jj & 7)) << 3);
        *reinterpret_cast<uint4*>(g_W0p + dst) = *reinterpret_cast<uint4*>(tmp);
        return;
    }
    i -= S1;
    const int S2 = NCTA * NT1 * 512;
    if (i < S2) {
        int bn = i / (NT1 * 512), r1 = i % (NT1 * 512);
        int T = r1 / 512, r2 = r1 & 511;
        int jj = r2 >> 3, u = r2 & 7;
        int R = (jj >> 4) * HH + bn * 16 + (jj & 15);
        // hh tiles first (T 0..31), then ih tiles (T 32..63)
        const float* s = (T < 32)
            ? W_hh1 + (size_t)R * HH + T * 64 + u * 8
            : W_ih1 + (size_t)R * HH + (T - 32) * 64 + u * 8;
        __half tmp[8];
        #pragma unroll
        for (int e = 0; e < 8; e++) tmp[e] = __float2half(s[e]);
        size_t dst = ((size_t)(bn * NT1 + T) * 64 + jj) * 64 + ((u ^ (jj & 7)) << 3);
        *reinterpret_cast<uint4*>(g_W1p + dst) = *reinterpret_cast<uint4*>(tmp);
        return;
    }
    i -= S2;
    const int S3 = 2 * 512;
    if (i < S3) {
        int kt = i / 512, r2 = i % 512;
        int r = r2 >> 3, u = r2 & 7;
        int j = kt * 64 + r;
        __half tmp[8];
        #pragma unroll
        for (int e = 0; e < 8; e++) {
            int b = u * 8 + e;
            tmp[e] = __float2half(j < HIN ? inputs[b * HIN + j] : 0.f);
        }
        *reinterpret_cast<uint4*>(g_xT + kt * TILE_H + swz_off(r, u, 0)) =
            *reinterpret_cast<uint4*>(tmp);
        return;
    }
    i -= S3;
    const int S4 = 32 * 512;
    if (i < S4) {
        int kt = i / 512, r2 = i % 512;
        int r = r2 >> 3, u = r2 & 7;
        int j = kt * 64 + r;
        __half tmp[8];
        #pragma unroll
        for (int e = 0; e < 8; e++)
            tmp[e] = __float2half(hiddens[(size_t)(u * 8 + e) * HH + j]);
        *reinterpret_cast<uint4*>(g_h0Ta + kt * TILE_H + swz_off(r, u, 0)) =
            *reinterpret_cast<uint4*>(tmp);
        return;
    }
    i -= S4;
    if (i < S4) {
        int kt = i / 512, r2 = i % 512;
        int r = r2 >> 3, u = r2 & 7;
        int j = kt * 64 + r;
        __half tmp[8];
        #pragma unroll
        for (int e = 0; e < 8; e++)
            tmp[e] = __float2half(hiddens[(size_t)BB * HH + (size_t)(u * 8 + e) * HH + j]);
        *reinterpret_cast<uint4*>(g_h1Ta + kt * TILE_H + swz_off(r, u, 0)) =
            *reinterpret_cast<uint4*>(tmp);
        return;
    }
    i -= S4;
    if (i < G4) { g_bias0[i] = b_ih0[i] + b_hh0[i]; return; }
    i -= G4;
    if (i < G4) { g_bias1[i] = b_ih1[i] + b_hh1[i]; return; }
    i -= G4;
    const int S7 = OUTD * HH / 8;
    if (i < S7) {
        float4 f0 = *reinterpret_cast<const float4*>(fc_w + (size_t)i * 8);
        float4 f1 = *reinterpret_cast<const float4*>(fc_w + (size_t)i * 8 + 4);
        uint4 u;
        *reinterpret_cast<__half2*>(&u.x) = __floats2half2_rn(f0.x, f0.y);
        *reinterpret_cast<__half2*>(&u.y) = __floats2half2_rn(f0.z, f0.w);
        *reinterpret_cast<__half2*>(&u.z) = __floats2half2_rn(f1.x, f1.y);
        *reinterpret_cast<__half2*>(&u.w) = __floats2half2_rn(f1.z, f1.w);
        reinterpret_cast<uint4*>(g_fcwh)[i] = u;
        return;
    }
    i -= S7;
    const int S8 = BB * HH / 4;
    if (i < S8) {
        reinterpret_cast<float4*>(g_c0)[i] =
            reinterpret_cast<const float4*>(cells)[i];
        return;
    }
    i -= S8;
    if (i < S8) {
        reinterpret_cast<float4*>(g_c1)[i] =
            reinterpret_cast<const float4*>(cells + (size_t)BB * HH)[i];
        return;
    }
}

// ---------------- sync primitives ----------------
__device__ __forceinline__ void spin_gpu(unsigned target) {
    unsigned v;
    do {
        asm volatile("ld.acquire.gpu.u32 %0, [%1];" : "=r"(v)
                     : "l"(&g_barcnt) : "memory");
    } while (v < target);
}
__device__ __forceinline__ void consumer_bar() {
    asm volatile("bar.sync 1, 512;" ::: "memory");
}
__device__ __forceinline__ void mbar_init(uint32_t bar, uint32_t cnt) {
    asm volatile("mbarrier.init.shared.b64 [%0], %1;" :: "r"(bar), "r"(cnt) : "memory");
}
__device__ __forceinline__ void mbar_expect_tx(uint32_t bar, uint32_t bytes) {
    asm volatile("mbarrier.arrive.expect_tx.shared.b64 _, [%0], %1;"
                 :: "r"(bar), "r"(bytes) : "memory");
}
__device__ __forceinline__ void mbar_arrive(uint32_t bar) {
    asm volatile("mbarrier.arrive.shared.b64 _, [%0];" :: "r"(bar) : "memory");
}
__device__ __forceinline__ void bulk_g2s(uint32_t dst, const void* src,
                                         uint32_t bytes, uint32_t bar) {
    asm volatile("cp.async.bulk.shared::cluster.global.mbarrier::complete_tx::bytes "
                 "[%0], [%1], %2, [%3];"
                 :: "r"(dst), "l"(src), "r"(bytes), "r"(bar) : "memory");
}
__device__ __forceinline__ void bulk_g2s_el(uint32_t dst, const void* src,
                                            uint32_t bytes, uint32_t bar) {
    uint64_t pol;
    asm volatile("createpolicy.fractional.L2::evict_last.b64 %0;" : "=l"(pol));
    asm volatile("cp.async.bulk.shared::cluster.global.mbarrier::complete_tx::bytes.L2::cache_hint "
                 "[%0], [%1], %2, [%3], %4;"
                 :: "r"(dst), "l"(src), "r"(bytes), "r"(bar), "l"(pol) : "memory");
}
__device__ __forceinline__ void mbar_wait(uint32_t bar, uint32_t parity) {
    asm volatile(
        "{\n\t.reg .pred P;\n"
        "W%=:\n\t"
        "mbarrier.try_wait.parity.acquire.cta.shared::cta.b64 P, [%0], %1, 0x989680;\n\t"
        "@P bra D%=;\n\t"
        "bra W%=;\n"
        "D%=:\n\t}"
        :: "r"(bar), "r"(parity) : "memory");
}
__device__ __forceinline__ void mma16816(float* c, uint32_t a0, uint32_t a1,
                                         uint32_t a2, uint32_t a3,
                                         uint32_t b0, uint32_t b1) {
    asm volatile(
        "mma.sync.aligned.m16n8k16.row.col.f32.f16.f16.f32 "
        "{%0,%1,%2,%3}, {%4,%5,%6,%7}, {%8,%9}, {%0,%1,%2,%3};\n"
        : "+f"(c[0]), "+f"(c[1]), "+f"(c[2]), "+f"(c[3])
        : "r"(a0), "r"(a1), "r"(a2), "r"(a3), "r"(b0), "r"(b1));
}

// ---------------- epilogue: 4-way k-merge + elementwise LSTM ----------------
template<bool WRITE_LIN>
__device__ __forceinline__ void epilogue(char* smc, float (*acc)[4][4],
                                         const float* __restrict__ bias,
                                         float* __restrict__ c_state,
                                         __half* __restrict__ hT_out,
                                         __half* __restrict__ h_lin,
                                         int bn, int tid) {
    float* Gs = reinterpret_cast<float*>(smc + GS_OFF);
    const int lane = tid & 31, warp = tid >> 5;
    const int wg = warp & 3, wm2 = (warp >> 2) & 1, wn2 = warp >> 3;
    const int row0 = wm2 * 32 + (lane >> 2);
    const int col0 = wn2 * 32 + (lane & 3) * 2;

    consumer_bar();                       // Gs safe to overwrite
    #pragma unroll
    for (int r = 0; r < 4; r++) {
        if (wg == r) {
            #pragma unroll
            for (int mi = 0; mi < 2; mi++) {
                #pragma unroll
                for (int nt = 0; nt < 4; nt++) {
                    int rr = row0 + mi * 16, cc = col0 + nt * 8;
                    if (r == 0) {
                        Gs[rr * 68 + cc]           = acc[mi][nt][0];
                        Gs[rr * 68 + cc + 1]       = acc[mi][nt][1];
                        Gs[(rr + 8) * 68 + cc]     = acc[mi][nt][2];
                        Gs[(rr + 8) * 68 + cc + 1] = acc[mi][nt][3];
                    } else {
                        Gs[rr * 68 + cc]           += acc[mi][nt][0];
                        Gs[rr * 68 + cc + 1]       += acc[mi][nt][1];
                        Gs[(rr + 8) * 68 + cc]     += acc[mi][nt][2];
                        Gs[(rr + 8) * 68 + cc + 1] += acc[mi][nt][3];
                    }
                }
            }
        }
        consumer_bar();
    }

    #pragma unroll
    for (int it = 0; it < 2; it++) {
        int sidx = tid + it * 512;
        int b = sidx >> 4, c = sidx & 15;
        int hcol = bn * 16 + c;
        float vi = Gs[b * 68 + c]      + bias[hcol];
        float vf = Gs[b * 68 + 16 + c] + bias[HH + hcol];
        float vg = Gs[b * 68 + 32 + c] + bias[2 * HH + hcol];
        float vo = Gs[b * 68 + 48 + c] + bias[3 * HH + hcol];
        float ii = 1.f / (1.f + __expf(-vi));
        float ff = 1.f / (1.f + __expf(-vf));
        float gg = tanhf(vg);
        float oo = 1.f / (1.f + __expf(-vo));
        int idx = b * HH + hcol;
        float c2 = ff * c_state[idx] + ii * gg;
        c_state[idx] = c2;
        __half hv = __float2half(oo * tanhf(c2));
        int kt = hcol >> 6, r = hcol & 63;
        hT_out[kt * TILE_H + swz_off(r, b >> 3, b & 7)] = hv;
        if (WRITE_LIN) h_lin[idx] = hv;
    }
    consumer_bar();                       // all stores done before release
}

// ---------------- fc phase ----------------
__device__ __forceinline__ void fc_phase(const __half* __restrict__ h1,
                                         const __half* __restrict__ fcw,
                                         const float* __restrict__ fc_b,
                                         float* __restrict__ out,
                                         int t, int tid, int bid) {
    int warp = tid >> 5;
    int gw = bid * 16 + warp;
    int lane = tid & 31;
    for (int task = gw; task < OUTD * BB; task += NCTA * 16) {
        int j = task % OUTD, b = task / OUTD;
        const uint4* w4 = reinterpret_cast<const uint4*>(fcw + (size_t)j * HH);
        const uint4* h4 = reinterpret_cast<const uint4*>(h1 + (size_t)b * HH);
        float s = 0.f;
        #pragma unroll
        for (int it = 0; it < 8; it++) {
            int k = lane + it * 32;
            uint4 wu = w4[k], hu = h4[k];
            const __half2* wp = reinterpret_cast<const __half2*>(&wu);
            const __half2* hp = reinterpret_cast<const __half2*>(&hu);
            #pragma unroll
            for (int e = 0; e < 4; e++) {
                float2 wf = __half22float2(wp[e]);
                float2 hf = __half22float2(hp[e]);
                s += wf.x * hf.x + wf.y * hf.y;
            }
        }
        #pragma unroll
        for (int o = 16; o; o >>= 1) s += __shfl_xor_sync(0xffffffffu, s, o);
        if (lane == 0) {
            float v = s + fc_b[j];
            v = fminf(fmaxf(v, -1.f), 1.f);
            out[(size_t)b * (TT * OUTD) + t * OUTD + j] = v;
            int kt = j >> 6, r = j & 63;
            g_xT[kt * TILE_H + swz_off(r, b >> 3, b & 7)] = __float2half(v);
        }
    }
}

// ---------------- one full step ----------------
__global__ void __launch_bounds__(NTHR, 1)
step_kernel(const __half* __restrict__ h0T_in, __half* __restrict__ h0T_out,
            const __half* __restrict__ h1T_in, __half* __restrict__ h1T_out,
            const float* __restrict__ fc_b, float* __restrict__ out, int t) {
    extern __shared__ char smc[];
    uint32_t smb = (uint32_t)__cvta_generic_to_shared(smc);
    const int tid = threadIdx.x, bn = blockIdx.x;
    const int lane = tid & 31, warp = tid >> 5;
    const uint32_t fullb  = smb + BAR_OFF;
    const uint32_t emptyb = smb + BAR_OFF + 128;

    if (tid == 0) {
        #pragma unroll
        for (int s = 0; s < NST; s++) {
            mbar_init(fullb + s * 8, 1);
            mbar_init(emptyb + s * 8, 16);
        }
    }
    __syncthreads();

    if (warp == 16) {
        // ---------------- producer: continuous tile stream 0..97 ----------------
        if (lane == 0) {
            const __half* W0 = g_W0p + (size_t)bn * NT0 * TILE_H;
            const __half* W1 = g_W1p + (size_t)bn * NT1 * TILE_H;
            auto issue = [&](int tg, const __half* act, const __half* wsrc) {
                int s = tg % NST;
                if (tg >= NST) mbar_wait(emptyb + s * 8, ((tg / NST) - 1) & 1);
                mbar_expect_tx(fullb + s * 8, STAGE);
                bulk_g2s(smb + s * STAGE, act, 8192, fullb + s * 8);
                bulk_g2s_el(smb + s * STAGE + 8192, wsrc, 8192, fullb + s * 8);
            };
            for (int tg = 0; tg < NT0; tg++) {
                const __half* act = (tg < NT0I) ? g_xT + (size_t)tg * TILE_H
                                                : h0T_in + (size_t)(tg - NT0I) * TILE_H;
                issue(tg, act, W0 + (size_t)tg * TILE_H);
            }
            for (int tp = 0; tp < 32; tp++)      // cell1 hh (no barrier needed)
                issue(NT0 + tp, h1T_in + (size_t)tp * TILE_H,
                      W1 + (size_t)tp * TILE_H);
            spin_gpu((unsigned)(2 * t + 1) * NCTA);   // gate on all cell0 epilogues
            for (int tp = 32; tp < 64; tp++)     // cell1 ih (reads h0T_out)
                issue(NT0 + tp, h0T_out + (size_t)(tp - 32) * TILE_H,
                      W1 + (size_t)tp * TILE_H);
        }
        return;
    }

    // ---------------- consumers: 16 warps, 2m x 2n x 4k split ----------------
    const int wg = warp & 3, wm2 = (warp >> 2) & 1, wn2 = warp >> 3;
    const int kk = wg * 16;
    const int q = lane >> 3;
    const int kbA = (q >> 1) * 8 + (lane & 7);
    const int arow = (kk + kbA) << 7;
    const int mc0 = wm2 * 32 + (q & 1) * 8;
    const int mc1 = mc0 + 16;
    const int aoff0 = arow + (((((mc0 >> 3) ^ (kbA & 7)) << 3)) << 1);
    const int aoff1 = arow + (((((mc1 >> 3) ^ (kbA & 7)) << 3)) << 1);
    const int jj0 = wn2 * 32 + (lane & 15);
    const int jj1 = jj0 + 16;
    const int klane = lane >> 4;
    const int woff0 = (jj0 << 7) + (((((klane + wg * 2) ^ (jj0 & 7)) << 3)) << 1);
    const int woff1 = (jj1 << 7) + (((((klane + wg * 2) ^ (jj1 & 7)) << 3)) << 1);

    float acc[2][4][4];
    auto zero_acc = [&]() {
        #pragma unroll
        for (int mi = 0; mi < 2; mi++)
            #pragma unroll
            for (int nt = 0; nt < 4; nt++)
                #pragma unroll
                for (int e = 0; e < 4; e++) acc[mi][nt][e] = 0.f;
    };
    auto consume = [&](int t0, int t1) {
        for (int tg = t0; tg < t1; tg++) {
            int s = tg % NST;
            mbar_wait(fullb + s * 8, (tg / NST) & 1);
            uint32_t abuf = smb + s * STAGE;
            uint32_t wbuf = abuf + 8192;
            uint32_t a0[4], a1[4], p[4], qq[4];
            asm volatile("ldmatrix.sync.aligned.m8n8.x4.trans.shared.b16 "
                         "{%0,%1,%2,%3}, [%4];\n"
                         : "=r"(a0[0]), "=r"(a0[1]), "=r"(a0[2]), "=r"(a0[3])
                         : "r"(abuf + aoff0));
            asm volatile("ldmatrix.sync.aligned.m8n8.x4.trans.shared.b16 "
                         "{%0,%1,%2,%3}, [%4];\n"
                         : "=r"(a1[0]), "=r"(a1[1]), "=r"(a1[2]), "=r"(a1[3])
                         : "r"(abuf + aoff1));
            asm volatile("ldmatrix.sync.aligned.m8n8.x4.shared.b16 "
                         "{%0,%1,%2,%3}, [%4];\n"
                         : "=r"(p[0]), "=r"(p[1]), "=r"(p[2]), "=r"(p[3])
                         : "r"(wbuf + woff0));
            asm volatile("ldmatrix.sync.aligned.m8n8.x4.shared.b16 "
                         "{%0,%1,%2,%3}, [%4];\n"
                         : "=r"(qq[0]), "=r"(qq[1]), "=r"(qq[2]), "=r"(qq[3])
                         : "r"(wbuf + woff1));
            #pragma unroll
            for (int mi = 0; mi < 2; mi++) {
                uint32_t* a = mi ? a1 : a0;
                mma16816(acc[mi][0], a[0], a[1], a[2], a[3], p[0], p[2]);
                mma16816(acc[mi][1], a[0], a[1], a[2], a[3], p[1], p[3]);
                mma16816(acc[mi][2], a[0], a[1], a[2], a[3], qq[0], qq[2]);
                mma16816(acc[mi][3], a[0], a[1], a[2], a[3], qq[1], qq[3]);
            }
            if (lane == 0) mbar_arrive(emptyb + s * 8);
        }
    };

    // cell0
    zero_acc();
    consume(0, NT0);
    epilogue<false>(smc, acc, g_bias0, g_c0, h0T_out, nullptr, bn, tid);
    if (tid == 0) {                       // release barrier 1 (producer-gated)
        __threadfence();
        atomicAdd(&g_barcnt, 1u);
    }
    // cell1 (hh tiles then ih tiles; ordering enforced by producer gate)
    zero_acc();
    consume(NT0, NT0 + NT1);
    epilogue<true>(smc, acc, g_bias1, g_c1, h1T_out, g_h1lin, bn, tid);
    if (tid == 0) {                       // release + wait barrier 2
        __threadfence();
        atomicAdd(&g_barcnt, 1u);
        spin_gpu((unsigned)(2 * t + 2) * NCTA);
    }
    consumer_bar();
    fc_phase(g_h1lin, g_fcwh, fc_b, out, t, tid, bn);
}

// ---------------- launch ----------------
extern "C" void kernel_launch(void* const* d_in, const int* in_sizes, int n_in,
                              void* d_out, int out_size) {
    (void)in_sizes; (void)n_in; (void)out_size;
    const float* inputs  = (const float*)d_in[0];
    const float* hiddens = (const float*)d_in[1];
    const float* cells   = (const float*)d_in[2];
    const float* W_ih0   = (const float*)d_in[3];
    const float* W_hh0   = (const float*)d_in[4];
    const float* b_ih0   = (const float*)d_in[5];
    const float* b_hh0   = (const float*)d_in[6];
    const float* W_ih1   = (const float*)d_in[7];
    const float* W_hh1   = (const float*)d_in[8];
    const float* b_ih1   = (const float*)d_in[9];
    const float* b_hh1   = (const float*)d_in[10];
    const float* fc_w    = (const float*)d_in[11];
    const float* fc_b    = (const float*)d_in[12];
    float* out = (float*)d_out;

    __half *p_h0a, *p_h0b, *p_h1a, *p_h1b;
    cudaGetSymbolAddress((void**)&p_h0a, g_h0Ta);
    cudaGetSymbolAddress((void**)&p_h0b, g_h0Tb);
    cudaGetSymbolAddress((void**)&p_h1a, g_h1Ta);
    cudaGetSymbolAddress((void**)&p_h1b, g_h1Tb);

    cudaFuncSetAttribute(step_kernel,
                         cudaFuncAttributeMaxDynamicSharedMemorySize, SMEM_BYTES);

    const long SETUP_N = 6555136;
    setup_kernel<<<(int)((SETUP_N + 255) / 256), 256>>>(
        inputs, hiddens, cells, W_ih0, W_hh0, b_ih0, b_hh0,
        W_ih1, W_hh1, b_ih1, b_hh1, fc_w);

    for (int t = 0; t < TT; t++) {
        __half* h0_in  = (t & 1) ? p_h0b : p_h0a;
        __half* h0_out = (t & 1) ? p_h0a : p_h0b;
        __half* h1_in  = (t & 1) ? p_h1b : p_h1a;
        __half* h1_out = (t & 1) ? p_h1a : p_h1b;
        step_kernel<<<NCTA, NTHR, SMEM_BYTES>>>(h0_in, h0_out, h1_in, h1_out,
                                                fc_b, out, t);
    }
}

// round 10
// speedup vs baseline: 5.5529x; 1.0506x over previous
#include <cuda_runtime.h>
#include <cuda_fp16.h>
#include <cstdint>
#include <math.h>

#define BB   64
#define HH   2048
#define HIN  66
#define TT   25
#define OUTD 66
#define G4   8192
#define NCTA 128
#define NTHR 544        // 16 consumer warps + 1 producer warp
#define NST  6
#define STAGE 32768     // 16KB act + 16KB weight (k=128 tile)
#define GS_OFF (NST * STAGE)          // 196608
#define BAR_OFF (GS_OFF + 17408)
#define SMEM_BYTES (BAR_OFF + 256)
#define NT0I 2
#define NT0  34         // 64-k granules cell0 (setup layout unchanged)
#define NT1  64
#define NT0T 17         // 128-k tiles cell0
#define NT1T 32         // 128-k tiles cell1 (first 16 hh, last 16 ih)
#define NTT  49
#define TILE_H 4096

// ---------------- device scratch ----------------
__device__ __align__(256) __half g_W0p[NCTA * NT0 * TILE_H];
__device__ __align__(256) __half g_W1p[NCTA * NT1 * TILE_H];
__device__ __align__(256) __half g_xT[2 * TILE_H];
__device__ __align__(256) __half g_h0Ta[32 * TILE_H], g_h0Tb[32 * TILE_H];
__device__ __align__(256) __half g_h1Ta[32 * TILE_H], g_h1Tb[32 * TILE_H];
__device__ __align__(256) __half g_h1lin[BB * HH];
__device__ __align__(256) __half g_fcwh[OUTD * HH];
__device__ __align__(256) float  g_bias0[G4], g_bias1[G4];
__device__ __align__(256) float  g_c0[BB * HH], g_c1[BB * HH];
__device__ unsigned g_barcnt;

__device__ __forceinline__ int swz_off(int row, int u, int e) {
    return row * 64 + ((u ^ (row & 7)) << 3) + e;
}

// ---------------- setup (layout identical to R9: W1 hh-first) ----------------
__global__ void setup_kernel(const float* __restrict__ inputs,
                             const float* __restrict__ hiddens,
                             const float* __restrict__ cells,
                             const float* __restrict__ W_ih0,
                             const float* __restrict__ W_hh0,
                             const float* __restrict__ b_ih0,
                             const float* __restrict__ b_hh0,
                             const float* __restrict__ W_ih1,
                             const float* __restrict__ W_hh1,
                             const float* __restrict__ b_ih1,
                             const float* __restrict__ b_hh1,
                             const float* __restrict__ fc_w) {
    int i = blockIdx.x * blockDim.x + threadIdx.x;
    if (i == 0) g_barcnt = 0;

    const int S1 = NCTA * NT0 * 512;
    if (i < S1) {
        int bn = i / (NT0 * 512), r1 = i % (NT0 * 512);
        int T = r1 / 512, r2 = r1 & 511;
        int jj = r2 >> 3, u = r2 & 7;
        int R = (jj >> 4) * HH + bn * 16 + (jj & 15);
        __half tmp[8];
        if (T < NT0I) {
            #pragma unroll
            for (int e = 0; e < 8; e++) {
                int c = T * 64 + u * 8 + e;
                tmp[e] = __float2half(c < HIN ? W_ih0[(size_t)R * HIN + c] : 0.f);
            }
        } else {
            const float* s = W_hh0 + (size_t)R * HH + (T - NT0I) * 64 + u * 8;
            #pragma unroll
            for (int e = 0; e < 8; e++) tmp[e] = __float2half(s[e]);
        }
        size_t dst = ((size_t)(bn * NT0 + T) * 64 + jj) * 64 + ((u ^ (jj & 7)) << 3);
        *reinterpret_cast<uint4*>(g_W0p + dst) = *reinterpret_cast<uint4*>(tmp);
        return;
    }
    i -= S1;
    const int S2 = NCTA * NT1 * 512;
    if (i < S2) {
        int bn = i / (NT1 * 512), r1 = i % (NT1 * 512);
        int T = r1 / 512, r2 = r1 & 511;
        int jj = r2 >> 3, u = r2 & 7;
        int R = (jj >> 4) * HH + bn * 16 + (jj & 15);
        const float* s = (T < 32)
            ? W_hh1 + (size_t)R * HH + T * 64 + u * 8
            : W_ih1 + (size_t)R * HH + (T - 32) * 64 + u * 8;
        __half tmp[8];
        #pragma unroll
        for (int e = 0; e < 8; e++) tmp[e] = __float2half(s[e]);
        size_t dst = ((size_t)(bn * NT1 + T) * 64 + jj) * 64 + ((u ^ (jj & 7)) << 3);
        *reinterpret_cast<uint4*>(g_W1p + dst) = *reinterpret_cast<uint4*>(tmp);
        return;
    }
    i -= S2;
    const int S3 = 2 * 512;
    if (i < S3) {
        int kt = i / 512, r2 = i % 512;
        int r = r2 >> 3, u = r2 & 7;
        int j = kt * 64 + r;
        __half tmp[8];
        #pragma unroll
        for (int e = 0; e < 8; e++) {
            int b = u * 8 + e;
            tmp[e] = __float2half(j < HIN ? inputs[b * HIN + j] : 0.f);
        }
        *reinterpret_cast<uint4*>(g_xT + kt * TILE_H + swz_off(r, u, 0)) =
            *reinterpret_cast<uint4*>(tmp);
        return;
    }
    i -= S3;
    const int S4 = 32 * 512;
    if (i < S4) {
        int kt = i / 512, r2 = i % 512;
        int r = r2 >> 3, u = r2 & 7;
        int j = kt * 64 + r;
        __half tmp[8];
        #pragma unroll
        for (int e = 0; e < 8; e++)
            tmp[e] = __float2half(hiddens[(size_t)(u * 8 + e) * HH + j]);
        *reinterpret_cast<uint4*>(g_h0Ta + kt * TILE_H + swz_off(r, u, 0)) =
            *reinterpret_cast<uint4*>(tmp);
        return;
    }
    i -= S4;
    if (i < S4) {
        int kt = i / 512, r2 = i % 512;
        int r = r2 >> 3, u = r2 & 7;
        int j = kt * 64 + r;
        __half tmp[8];
        #pragma unroll
        for (int e = 0; e < 8; e++)
            tmp[e] = __float2half(hiddens[(size_t)BB * HH + (size_t)(u * 8 + e) * HH + j]);
        *reinterpret_cast<uint4*>(g_h1Ta + kt * TILE_H + swz_off(r, u, 0)) =
            *reinterpret_cast<uint4*>(tmp);
        return;
    }
    i -= S4;
    if (i < G4) { g_bias0[i] = b_ih0[i] + b_hh0[i]; return; }
    i -= G4;
    if (i < G4) { g_bias1[i] = b_ih1[i] + b_hh1[i]; return; }
    i -= G4;
    const int S7 = OUTD * HH / 8;
    if (i < S7) {
        float4 f0 = *reinterpret_cast<const float4*>(fc_w + (size_t)i * 8);
        float4 f1 = *reinterpret_cast<const float4*>(fc_w + (size_t)i * 8 + 4);
        uint4 u;
        *reinterpret_cast<__half2*>(&u.x) = __floats2half2_rn(f0.x, f0.y);
        *reinterpret_cast<__half2*>(&u.y) = __floats2half2_rn(f0.z, f0.w);
        *reinterpret_cast<__half2*>(&u.z) = __floats2half2_rn(f1.x, f1.y);
        *reinterpret_cast<__half2*>(&u.w) = __floats2half2_rn(f1.z, f1.w);
        reinterpret_cast<uint4*>(g_fcwh)[i] = u;
        return;
    }
    i -= S7;
    const int S8 = BB * HH / 4;
    if (i < S8) {
        reinterpret_cast<float4*>(g_c0)[i] =
            reinterpret_cast<const float4*>(cells)[i];
        return;
    }
    i -= S8;
    if (i < S8) {
        reinterpret_cast<float4*>(g_c1)[i] =
            reinterpret_cast<const float4*>(cells + (size_t)BB * HH)[i];
        return;
    }
}

// ---------------- sync primitives ----------------
__device__ __forceinline__ void spin_gpu(unsigned target) {
    unsigned v;
    do {
        asm volatile("ld.acquire.gpu.u32 %0, [%1];" : "=r"(v)
                     : "l"(&g_barcnt) : "memory");
    } while (v < target);
}
__device__ __forceinline__ void consumer_bar() {
    asm volatile("bar.sync 1, 512;" ::: "memory");
}
__device__ __forceinline__ void mbar_init(uint32_t bar, uint32_t cnt) {
    asm volatile("mbarrier.init.shared.b64 [%0], %1;" :: "r"(bar), "r"(cnt) : "memory");
}
__device__ __forceinline__ void mbar_expect_tx(uint32_t bar, uint32_t bytes) {
    asm volatile("mbarrier.arrive.expect_tx.shared.b64 _, [%0], %1;"
                 :: "r"(bar), "r"(bytes) : "memory");
}
__device__ __forceinline__ void mbar_arrive(uint32_t bar) {
    asm volatile("mbarrier.arrive.shared.b64 _, [%0];" :: "r"(bar) : "memory");
}
__device__ __forceinline__ void bulk_g2s(uint32_t dst, const void* src,
                                         uint32_t bytes, uint32_t bar) {
    asm volatile("cp.async.bulk.shared::cluster.global.mbarrier::complete_tx::bytes "
                 "[%0], [%1], %2, [%3];"
                 :: "r"(dst), "l"(src), "r"(bytes), "r"(bar) : "memory");
}
// evict_last: ONLY for W1p (64 MB, under the evict-last class capacity)
__device__ __forceinline__ void bulk_g2s_el(uint32_t dst, const void* src,
                                            uint32_t bytes, uint32_t bar) {
    uint64_t pol;
    asm volatile("createpolicy.fractional.L2::evict_last.b64 %0;" : "=l"(pol));
    asm volatile("cp.async.bulk.shared::cluster.global.mbarrier::complete_tx::bytes.L2::cache_hint "
                 "[%0], [%1], %2, [%3], %4;"
                 :: "r"(dst), "l"(src), "r"(bytes), "r"(bar), "l"(pol) : "memory");
}
__device__ __forceinline__ void mbar_wait(uint32_t bar, uint32_t parity) {
    asm volatile(
        "{\n\t.reg .pred P;\n"
        "W%=:\n\t"
        "mbarrier.try_wait.parity.acquire.cta.shared::cta.b64 P, [%0], %1, 0x989680;\n\t"
        "@P bra D%=;\n\t"
        "bra W%=;\n"
        "D%=:\n\t}"
        :: "r"(bar), "r"(parity) : "memory");
}
__device__ __forceinline__ void mma16816(float* c, uint32_t a0, uint32_t a1,
                                         uint32_t a2, uint32_t a3,
                                         uint32_t b0, uint32_t b1) {
    asm volatile(
        "mma.sync.aligned.m16n8k16.row.col.f32.f16.f16.f32 "
        "{%0,%1,%2,%3}, {%4,%5,%6,%7}, {%8,%9}, {%0,%1,%2,%3};\n"
        : "+f"(c[0]), "+f"(c[1]), "+f"(c[2]), "+f"(c[3])
        : "r"(a0), "r"(a1), "r"(a2), "r"(a3), "r"(b0), "r"(b1));
}

// ---------------- epilogue: 4-way k-merge + elementwise LSTM ----------------
template<bool WRITE_LIN>
__device__ __forceinline__ void epilogue(char* smc, float (*acc)[4][4],
                                         const float* __restrict__ bias,
                                         float* __restrict__ c_state,
                                         __half* __restrict__ hT_out,
                                         __half* __restrict__ h_lin,
                                         int bn, int tid) {
    float* Gs = reinterpret_cast<float*>(smc + GS_OFF);
    const int lane = tid & 31, warp = tid >> 5;
    const int wg = warp & 3, wm2 = (warp >> 2) & 1, wn2 = warp >> 3;
    const int row0 = wm2 * 32 + (lane >> 2);
    const int col0 = wn2 * 32 + (lane & 3) * 2;

    consumer_bar();
    #pragma unroll
    for (int r = 0; r < 4; r++) {
        if (wg == r) {
            #pragma unroll
            for (int mi = 0; mi < 2; mi++) {
                #pragma unroll
                for (int nt = 0; nt < 4; nt++) {
                    int rr = row0 + mi * 16, cc = col0 + nt * 8;
                    if (r == 0) {
                        Gs[rr * 68 + cc]           = acc[mi][nt][0];
                        Gs[rr * 68 + cc + 1]       = acc[mi][nt][1];
                        Gs[(rr + 8) * 68 + cc]     = acc[mi][nt][2];
                        Gs[(rr + 8) * 68 + cc + 1] = acc[mi][nt][3];
                    } else {
                        Gs[rr * 68 + cc]           += acc[mi][nt][0];
                        Gs[rr * 68 + cc + 1]       += acc[mi][nt][1];
                        Gs[(rr + 8) * 68 + cc]     += acc[mi][nt][2];
                        Gs[(rr + 8) * 68 + cc + 1] += acc[mi][nt][3];
                    }
                }
            }
        }
        consumer_bar();
    }

    #pragma unroll
    for (int it = 0; it < 2; it++) {
        int sidx = tid + it * 512;
        int b = sidx >> 4, c = sidx & 15;
        int hcol = bn * 16 + c;
        float vi = Gs[b * 68 + c]      + bias[hcol];
        float vf = Gs[b * 68 + 16 + c] + bias[HH + hcol];
        float vg = Gs[b * 68 + 32 + c] + bias[2 * HH + hcol];
        float vo = Gs[b * 68 + 48 + c] + bias[3 * HH + hcol];
        float ii = 1.f / (1.f + __expf(-vi));
        float ff = 1.f / (1.f + __expf(-vf));
        float gg = tanhf(vg);
        float oo = 1.f / (1.f + __expf(-vo));
        int idx = b * HH + hcol;
        float c2 = ff * c_state[idx] + ii * gg;
        c_state[idx] = c2;
        __half hv = __float2half(oo * tanhf(c2));
        int kt = hcol >> 6, r = hcol & 63;
        hT_out[kt * TILE_H + swz_off(r, b >> 3, b & 7)] = hv;
        if (WRITE_LIN) h_lin[idx] = hv;
    }
    consumer_bar();
}

// ---------------- fc phase ----------------
__device__ __forceinline__ void fc_phase(const __half* __restrict__ h1,
                                         const __half* __restrict__ fcw,
                                         const float* __restrict__ fc_b,
                                         float* __restrict__ out,
                                         int t, int tid, int bid) {
    int warp = tid >> 5;
    int gw = bid * 16 + warp;
    int lane = tid & 31;
    for (int task = gw; task < OUTD * BB; task += NCTA * 16) {
        int j = task % OUTD, b = task / OUTD;
        const uint4* w4 = reinterpret_cast<const uint4*>(fcw + (size_t)j * HH);
        const uint4* h4 = reinterpret_cast<const uint4*>(h1 + (size_t)b * HH);
        float s = 0.f;
        #pragma unroll
        for (int it = 0; it < 8; it++) {
            int k = lane + it * 32;
            uint4 wu = w4[k], hu = h4[k];
            const __half2* wp = reinterpret_cast<const __half2*>(&wu);
            const __half2* hp = reinterpret_cast<const __half2*>(&hu);
            #pragma unroll
            for (int e = 0; e < 4; e++) {
                float2 wf = __half22float2(wp[e]);
                float2 hf = __half22float2(hp[e]);
                s += wf.x * hf.x + wf.y * hf.y;
            }
        }
        #pragma unroll
        for (int o = 16; o; o >>= 1) s += __shfl_xor_sync(0xffffffffu, s, o);
        if (lane == 0) {
            float v = s + fc_b[j];
            v = fminf(fmaxf(v, -1.f), 1.f);
            out[(size_t)b * (TT * OUTD) + t * OUTD + j] = v;
            int kt = j >> 6, r = j & 63;
            g_xT[kt * TILE_H + swz_off(r, b >> 3, b & 7)] = __float2half(v);
        }
    }
}

// ---------------- one full step ----------------
__global__ void __launch_bounds__(NTHR, 1)
step_kernel(const __half* __restrict__ h0T_in, __half* __restrict__ h0T_out,
            const __half* __restrict__ h1T_in, __half* __restrict__ h1T_out,
            const float* __restrict__ fc_b, float* __restrict__ out, int t) {
    extern __shared__ char smc[];
    uint32_t smb = (uint32_t)__cvta_generic_to_shared(smc);
    const int tid = threadIdx.x, bn = blockIdx.x;
    const int lane = tid & 31, warp = tid >> 5;
    const uint32_t fullb  = smb + BAR_OFF;
    const uint32_t emptyb = smb + BAR_OFF + 128;

    if (tid == 0) {
        #pragma unroll
        for (int s = 0; s < NST; s++) {
            mbar_init(fullb + s * 8, 1);
            mbar_init(emptyb + s * 8, 16);
        }
    }
    __syncthreads();

    if (warp == 16) {
        // ---------------- producer: 49 k128-tiles, continuous stream ----------
        if (lane == 0) {
            const __half* W0 = g_W0p + (size_t)bn * NT0 * TILE_H;
            const __half* W1 = g_W1p + (size_t)bn * NT1 * TILE_H;
            auto issue = [&](int tg, const __half* act, const __half* wsrc,
                             bool wlast) {
                int s = tg % NST;
                if (tg >= NST) mbar_wait(emptyb + s * 8, ((tg / NST) - 1) & 1);
                mbar_expect_tx(fullb + s * 8, STAGE);
                bulk_g2s(smb + s * STAGE, act, 16384, fullb + s * 8);
                if (wlast)
                    bulk_g2s_el(smb + s * STAGE + 16384, wsrc, 16384, fullb + s * 8);
                else
                    bulk_g2s(smb + s * STAGE + 16384, wsrc, 16384, fullb + s * 8);
            };
            // cell0: tile 0 = x (2 ktiles = 16 KB), tiles 1..16 = h0T_in
            issue(0, g_xT, W0, false);
            for (int tg = 1; tg < NT0T; tg++)
                issue(tg, h0T_in + (size_t)(tg - 1) * 8192,
                      W0 + (size_t)tg * 8192, false);
            // cell1 hh: tiles 17..32 (no dependency on cell0)
            for (int tp = 0; tp < 16; tp++)
                issue(NT0T + tp, h1T_in + (size_t)tp * 8192,
                      W1 + (size_t)tp * 8192, true);
            spin_gpu((unsigned)(2 * t + 1) * NCTA);   // all cell0 epilogues done
            // cell1 ih: tiles 33..48 (reads h0T_out)
            for (int tp = 16; tp < 32; tp++)
                issue(NT0T + tp, h0T_out + (size_t)(tp - 16) * 8192,
                      W1 + (size_t)tp * 8192, true);
        }
        return;
    }

    // ---------------- consumers: 16 warps, 2m x 2n x 4k split, 2 k64 blocks ----
    const int wg = warp & 3, wm2 = (warp >> 2) & 1, wn2 = warp >> 3;
    const int kk = wg * 16;
    const int q = lane >> 3;
    const int kbA = (q >> 1) * 8 + (lane & 7);
    const int arow = (kk + kbA) << 7;
    const int mc0 = wm2 * 32 + (q & 1) * 8;
    const int mc1 = mc0 + 16;
    const int aoff0 = arow + (((((mc0 >> 3) ^ (kbA & 7)) << 3)) << 1);
    const int aoff1 = arow + (((((mc1 >> 3) ^ (kbA & 7)) << 3)) << 1);
    const int jj0 = wn2 * 32 + (lane & 15);
    const int jj1 = jj0 + 16;
    const int klane = lane >> 4;
    const int woff0 = (jj0 << 7) + (((((klane + wg * 2) ^ (jj0 & 7)) << 3)) << 1);
    const int woff1 = (jj1 << 7) + (((((klane + wg * 2) ^ (jj1 & 7)) << 3)) << 1);

    float acc[2][4][4];
    auto zero_acc = [&]() {
        #pragma unroll
        for (int mi = 0; mi < 2; mi++)
            #pragma unroll
            for (int nt = 0; nt < 4; nt++)
                #pragma unroll
                for (int e = 0; e < 4; e++) acc[mi][nt][e] = 0.f;
    };
    auto consume = [&](int t0, int t1) {
        for (int tg = t0; tg < t1; tg++) {
            int s = tg % NST;
            mbar_wait(fullb + s * 8, (tg / NST) & 1);
            uint32_t abase = smb + s * STAGE;
            uint32_t wbase = abase + 16384;
            #pragma unroll
            for (int blk = 0; blk < 2; blk++) {
                uint32_t abuf = abase + blk * 8192;
                uint32_t wbuf = wbase + blk * 8192;
                uint32_t a0[4], a1[4], p[4], qq[4];
                asm volatile("ldmatrix.sync.aligned.m8n8.x4.trans.shared.b16 "
                             "{%0,%1,%2,%3}, [%4];\n"
                             : "=r"(a0[0]), "=r"(a0[1]), "=r"(a0[2]), "=r"(a0[3])
                             : "r"(abuf + aoff0));
                asm volatile("ldmatrix.sync.aligned.m8n8.x4.trans.shared.b16 "
                             "{%0,%1,%2,%3}, [%4];\n"
                             : "=r"(a1[0]), "=r"(a1[1]), "=r"(a1[2]), "=r"(a1[3])
                             : "r"(abuf + aoff1));
                asm volatile("ldmatrix.sync.aligned.m8n8.x4.shared.b16 "
                             "{%0,%1,%2,%3}, [%4];\n"
                             : "=r"(p[0]), "=r"(p[1]), "=r"(p[2]), "=r"(p[3])
                             : "r"(wbuf + woff0));
                asm volatile("ldmatrix.sync.aligned.m8n8.x4.shared.b16 "
                             "{%0,%1,%2,%3}, [%4];\n"
                             : "=r"(qq[0]), "=r"(qq[1]), "=r"(qq[2]), "=r"(qq[3])
                             : "r"(wbuf + woff1));
                #pragma unroll
                for (int mi = 0; mi < 2; mi++) {
                    uint32_t* a = mi ? a1 : a0;
                    mma16816(acc[mi][0], a[0], a[1], a[2], a[3], p[0], p[2]);
                    mma16816(acc[mi][1], a[0], a[1], a[2], a[3], p[1], p[3]);
                    mma16816(acc[mi][2], a[0], a[1], a[2], a[3], qq[0], qq[2]);
                    mma16816(acc[mi][3], a[0], a[1], a[2], a[3], qq[1], qq[3]);
                }
            }
            if (lane == 0) mbar_arrive(emptyb + s * 8);
        }
    };

    // cell0
    zero_acc();
    consume(0, NT0T);
    epilogue<false>(smc, acc, g_bias0, g_c0, h0T_out, nullptr, bn, tid);
    if (tid == 0) {
        __threadfence();
        atomicAdd(&g_barcnt, 1u);
    }
    // cell1 (hh tiles then ih tiles; ordering enforced by producer gate)
    zero_acc();
    consume(NT0T, NTT);
    epilogue<true>(smc, acc, g_bias1, g_c1, h1T_out, g_h1lin, bn, tid);
    if (tid == 0) {
        __threadfence();
        atomicAdd(&g_barcnt, 1u);
        spin_gpu((unsigned)(2 * t + 2) * NCTA);
    }
    consumer_bar();
    fc_phase(g_h1lin, g_fcwh, fc_b, out, t, tid, bn);
}

// ---------------- launch ----------------
extern "C" void kernel_launch(void* const* d_in, const int* in_sizes, int n_in,
                              void* d_out, int out_size) {
    (void)in_sizes; (void)n_in; (void)out_size;
    const float* inputs  = (const float*)d_in[0];
    const float* hiddens = (const float*)d_in[1];
    const float* cells   = (const float*)d_in[2];
    const float* W_ih0   = (const float*)d_in[3];
    const float* W_hh0   = (const float*)d_in[4];
    const float* b_ih0   = (const float*)d_in[5];
    const float* b_hh0   = (const float*)d_in[6];
    const float* W_ih1   = (const float*)d_in[7];
    const float* W_hh1   = (const float*)d_in[8];
    const float* b_ih1   = (const float*)d_in[9];
    const float* b_hh1   = (const float*)d_in[10];
    const float* fc_w    = (const float*)d_in[11];
    const float* fc_b    = (const float*)d_in[12];
    float* out = (float*)d_out;

    __half *p_h0a, *p_h0b, *p_h1a, *p_h1b;
    cudaGetSymbolAddress((void**)&p_h0a, g_h0Ta);
    cudaGetSymbolAddress((void**)&p_h0b, g_h0Tb);
    cudaGetSymbolAddress((void**)&p_h1a, g_h1Ta);
    cudaGetSymbolAddress((void**)&p_h1b, g_h1Tb);

    cudaFuncSetAttribute(step_kernel,
                         cudaFuncAttributeMaxDynamicSharedMemorySize, SMEM_BYTES);

    const long SETUP_N = 6555136;
    setup_kernel<<<(int)((SETUP_N + 255) / 256), 256>>>(
        inputs, hiddens, cells, W_ih0, W_hh0, b_ih0, b_hh0,
        W_ih1, W_hh1, b_ih1, b_hh1, fc_w);

    for (int t = 0; t < TT; t++) {
        __half* h0_in  = (t & 1) ? p_h0b : p_h0a;
        __half* h0_out = (t & 1) ? p_h0a : p_h0b;
        __half* h1_in  = (t & 1) ? p_h1b : p_h1a;
        __half* h1_out = (t & 1) ? p_h1a : p_h1b;
        step_kernel<<<NCTA, NTHR, SMEM_BYTES>>>(h0_in, h0_out, h1_in, h1_out,
                                                fc_b, out, t);
    }
}

// round 11
// speedup vs baseline: 5.9403x; 1.0698x over previous
#include <cuda_runtime.h>
#include <cuda_fp16.h>
#include <cstdint>
#include <math.h>

#define BB   64
#define HH   2048
#define HIN  66
#define TT   25
#define OUTD 66
#define G4   8192
#define NCTA 128
#define NTHR 544        // 16 consumer warps + 1 producer warp
#define NST  6
#define STAGE 32768     // 16KB act + 16KB weight (k=128 tile)
#define GS_OFF (NST * STAGE)
#define BAR_OFF (GS_OFF + 17408)
#define SMEM_BYTES (BAR_OFF + 256)
#define NT0  34         // 64-k granules cell0 (hh first: 0..31, ih: 32..33)
#define NT1  64         // 64-k granules cell1 (hh: 0..31, ih: 32..63)
#define NT0T 17
#define NTT  49
#define TILE_H 4096

// ---------------- device scratch ----------------
__device__ __align__(256) __half g_W0p[NCTA * NT0 * TILE_H];
__device__ __align__(256) __half g_W1p[NCTA * NT1 * TILE_H];
__device__ __align__(256) __half g_xT[2 * TILE_H];
__device__ __align__(256) __half g_h0Ta[32 * TILE_H], g_h0Tb[32 * TILE_H];
__device__ __align__(256) __half g_h1Ta[32 * TILE_H], g_h1Tb[32 * TILE_H];
__device__ __align__(256) __half g_h1lin[BB * HH];
__device__ __align__(256) __half g_fcwh[OUTD * HH];
__device__ __align__(256) float  g_bias0[G4], g_bias1[G4];
__device__ __align__(256) float  g_c0[BB * HH], g_c1[BB * HH];
__device__ unsigned g_barcnt;

__device__ __forceinline__ int swz_off(int row, int u, int e) {
    return row * 64 + ((u ^ (row & 7)) << 3) + e;
}

// ---------------- setup (W0 now hh-first; W1 hh-first as before) ----------------
__global__ void setup_kernel(const float* __restrict__ inputs,
                             const float* __restrict__ hiddens,
                             const float* __restrict__ cells,
                             const float* __restrict__ W_ih0,
                             const float* __restrict__ W_hh0,
                             const float* __restrict__ b_ih0,
                             const float* __restrict__ b_hh0,
                             const float* __restrict__ W_ih1,
                             const float* __restrict__ W_hh1,
                             const float* __restrict__ b_ih1,
                             const float* __restrict__ b_hh1,
                             const float* __restrict__ fc_w) {
    int i = blockIdx.x * blockDim.x + threadIdx.x;
    if (i == 0) g_barcnt = 0;

    const int S1 = NCTA * NT0 * 512;
    if (i < S1) {
        int bn = i / (NT0 * 512), r1 = i % (NT0 * 512);
        int T = r1 / 512, r2 = r1 & 511;
        int jj = r2 >> 3, u = r2 & 7;
        int R = (jj >> 4) * HH + bn * 16 + (jj & 15);
        __half tmp[8];
        if (T < 32) {                       // hh granules first
            const float* s = W_hh0 + (size_t)R * HH + T * 64 + u * 8;
            #pragma unroll
            for (int e = 0; e < 8; e++) tmp[e] = __float2half(s[e]);
        } else {                            // ih granules (padded 66->128)
            #pragma unroll
            for (int e = 0; e < 8; e++) {
                int c = (T - 32) * 64 + u * 8 + e;
                tmp[e] = __float2half(c < HIN ? W_ih0[(size_t)R * HIN + c] : 0.f);
            }
        }
        size_t dst = ((size_t)(bn * NT0 + T) * 64 + jj) * 64 + ((u ^ (jj & 7)) << 3);
        *reinterpret_cast<uint4*>(g_W0p + dst) = *reinterpret_cast<uint4*>(tmp);
        return;
    }
    i -= S1;
    const int S2 = NCTA * NT1 * 512;
    if (i < S2) {
        int bn = i / (NT1 * 512), r1 = i % (NT1 * 512);
        int T = r1 / 512, r2 = r1 & 511;
        int jj = r2 >> 3, u = r2 & 7;
        int R = (jj >> 4) * HH + bn * 16 + (jj & 15);
        const float* s = (T < 32)
            ? W_hh1 + (size_t)R * HH + T * 64 + u * 8
            : W_ih1 + (size_t)R * HH + (T - 32) * 64 + u * 8;
        __half tmp[8];
        #pragma unroll
        for (int e = 0; e < 8; e++) tmp[e] = __float2half(s[e]);
        size_t dst = ((size_t)(bn * NT1 + T) * 64 + jj) * 64 + ((u ^ (jj & 7)) << 3);
        *reinterpret_cast<uint4*>(g_W1p + dst) = *reinterpret_cast<uint4*>(tmp);
        return;
    }
    i -= S2;
    const int S3 = 2 * 512;
    if (i < S3) {
        int kt = i / 512, r2 = i % 512;
        int r = r2 >> 3, u = r2 & 7;
        int j = kt * 64 + r;
        __half tmp[8];
        #pragma unroll
        for (int e = 0; e < 8; e++) {
            int b = u * 8 + e;
            tmp[e] = __float2half(j < HIN ? inputs[b * HIN + j] : 0.f);
        }
        *reinterpret_cast<uint4*>(g_xT + kt * TILE_H + swz_off(r, u, 0)) =
            *reinterpret_cast<uint4*>(tmp);
        return;
    }
    i -= S3;
    const int S4 = 32 * 512;
    if (i < S4) {
        int kt = i / 512, r2 = i % 512;
        int r = r2 >> 3, u = r2 & 7;
        int j = kt * 64 + r;
        __half tmp[8];
        #pragma unroll
        for (int e = 0; e < 8; e++)
            tmp[e] = __float2half(hiddens[(size_t)(u * 8 + e) * HH + j]);
        *reinterpret_cast<uint4*>(g_h0Ta + kt * TILE_H + swz_off(r, u, 0)) =
            *reinterpret_cast<uint4*>(tmp);
        return;
    }
    i -= S4;
    if (i < S4) {
        int kt = i / 512, r2 = i % 512;
        int r = r2 >> 3, u = r2 & 7;
        int j = kt * 64 + r;
        __half tmp[8];
        #pragma unroll
        for (int e = 0; e < 8; e++)
            tmp[e] = __float2half(hiddens[(size_t)BB * HH + (size_t)(u * 8 + e) * HH + j]);
        *reinterpret_cast<uint4*>(g_h1Ta + kt * TILE_H + swz_off(r, u, 0)) =
            *reinterpret_cast<uint4*>(tmp);
        return;
    }
    i -= S4;
    if (i < G4) { g_bias0[i] = b_ih0[i] + b_hh0[i]; return; }
    i -= G4;
    if (i < G4) { g_bias1[i] = b_ih1[i] + b_hh1[i]; return; }
    i -= G4;
    const int S7 = OUTD * HH / 8;
    if (i < S7) {
        float4 f0 = *reinterpret_cast<const float4*>(fc_w + (size_t)i * 8);
        float4 f1 = *reinterpret_cast<const float4*>(fc_w + (size_t)i * 8 + 4);
        uint4 u;
        *reinterpret_cast<__half2*>(&u.x) = __floats2half2_rn(f0.x, f0.y);
        *reinterpret_cast<__half2*>(&u.y) = __floats2half2_rn(f0.z, f0.w);
        *reinterpret_cast<__half2*>(&u.z) = __floats2half2_rn(f1.x, f1.y);
        *reinterpret_cast<__half2*>(&u.w) = __floats2half2_rn(f1.z, f1.w);
        reinterpret_cast<uint4*>(g_fcwh)[i] = u;
        return;
    }
    i -= S7;
    const int S8 = BB * HH / 4;
    if (i < S8) {
        reinterpret_cast<float4*>(g_c0)[i] =
            reinterpret_cast<const float4*>(cells)[i];
        return;
    }
    i -= S8;
    if (i < S8) {
        reinterpret_cast<float4*>(g_c1)[i] =
            reinterpret_cast<const float4*>(cells + (size_t)BB * HH)[i];
        return;
    }
}

// ---------------- sync primitives ----------------
__device__ __forceinline__ void spin_gpu(unsigned target) {
    unsigned v;
    do {
        asm volatile("ld.acquire.gpu.u32 %0, [%1];" : "=r"(v)
                     : "l"(&g_barcnt) : "memory");
    } while (v < target);
}
__device__ __forceinline__ void consumer_bar() {
    asm volatile("bar.sync 1, 512;" ::: "memory");
}
__device__ __forceinline__ void mbar_init(uint32_t bar, uint32_t cnt) {
    asm volatile("mbarrier.init.shared.b64 [%0], %1;" :: "r"(bar), "r"(cnt) : "memory");
}
__device__ __forceinline__ void mbar_expect_tx(uint32_t bar, uint32_t bytes) {
    asm volatile("mbarrier.arrive.expect_tx.shared.b64 _, [%0], %1;"
                 :: "r"(bar), "r"(bytes) : "memory");
}
__device__ __forceinline__ void mbar_arrive(uint32_t bar) {
    asm volatile("mbarrier.arrive.shared.b64 _, [%0];" :: "r"(bar) : "memory");
}
__device__ __forceinline__ void bulk_g2s(uint32_t dst, const void* src,
                                         uint32_t bytes, uint32_t bar) {
    asm volatile("cp.async.bulk.shared::cluster.global.mbarrier::complete_tx::bytes "
                 "[%0], [%1], %2, [%3];"
                 :: "r"(dst), "l"(src), "r"(bytes), "r"(bar) : "memory");
}
__device__ __forceinline__ void mbar_wait(uint32_t bar, uint32_t parity) {
    asm volatile(
        "{\n\t.reg .pred P;\n"
        "W%=:\n\t"
        "mbarrier.try_wait.parity.acquire.cta.shared::cta.b64 P, [%0], %1, 0x989680;\n\t"
        "@P bra D%=;\n\t"
        "bra W%=;\n"
        "D%=:\n\t}"
        :: "r"(bar), "r"(parity) : "memory");
}
__device__ __forceinline__ void mma16816(float* c, uint32_t a0, uint32_t a1,
                                         uint32_t a2, uint32_t a3,
                                         uint32_t b0, uint32_t b1) {
    asm volatile(
        "mma.sync.aligned.m16n8k16.row.col.f32.f16.f16.f32 "
        "{%0,%1,%2,%3}, {%4,%5,%6,%7}, {%8,%9}, {%0,%1,%2,%3};\n"
        : "+f"(c[0]), "+f"(c[1]), "+f"(c[2]), "+f"(c[3])
        : "r"(a0), "r"(a1), "r"(a2), "r"(a3), "r"(b0), "r"(b1));
}

// ---------------- epilogue: 4-way k-merge + elementwise LSTM ----------------
template<bool WRITE_LIN>
__device__ __forceinline__ void epilogue(char* smc, float (*acc)[4][4],
                                         const float* __restrict__ bias,
                                         float* __restrict__ c_state,
                                         __half* __restrict__ hT_out,
                                         __half* __restrict__ h_lin,
                                         int bn, int tid) {
    float* Gs = reinterpret_cast<float*>(smc + GS_OFF);
    const int lane = tid & 31, warp = tid >> 5;
    const int wg = warp & 3, wm2 = (warp >> 2) & 1, wn2 = warp >> 3;
    const int row0 = wm2 * 32 + (lane >> 2);
    const int col0 = wn2 * 32 + (lane & 3) * 2;

    consumer_bar();
    #pragma unroll
    for (int r = 0; r < 4; r++) {
        if (wg == r) {
            #pragma unroll
            for (int mi = 0; mi < 2; mi++) {
                #pragma unroll
                for (int nt = 0; nt < 4; nt++) {
                    int rr = row0 + mi * 16, cc = col0 + nt * 8;
                    if (r == 0) {
                        Gs[rr * 68 + cc]           = acc[mi][nt][0];
                        Gs[rr * 68 + cc + 1]       = acc[mi][nt][1];
                        Gs[(rr + 8) * 68 + cc]     = acc[mi][nt][2];
                        Gs[(rr + 8) * 68 + cc + 1] = acc[mi][nt][3];
                    } else {
                        Gs[rr * 68 + cc]           += acc[mi][nt][0];
                        Gs[rr * 68 + cc + 1]       += acc[mi][nt][1];
                        Gs[(rr + 8) * 68 + cc]     += acc[mi][nt][2];
                        Gs[(rr + 8) * 68 + cc + 1] += acc[mi][nt][3];
                    }
                }
            }
        }
        consumer_bar();
    }

    #pragma unroll
    for (int it = 0; it < 2; it++) {
        int sidx = tid + it * 512;
        int b = sidx >> 4, c = sidx & 15;
        int hcol = bn * 16 + c;
        float vi = Gs[b * 68 + c]      + bias[hcol];
        float vf = Gs[b * 68 + 16 + c] + bias[HH + hcol];
        float vg = Gs[b * 68 + 32 + c] + bias[2 * HH + hcol];
        float vo = Gs[b * 68 + 48 + c] + bias[3 * HH + hcol];
        float ii = 1.f / (1.f + __expf(-vi));
        float ff = 1.f / (1.f + __expf(-vf));
        float gg = tanhf(vg);
        float oo = 1.f / (1.f + __expf(-vo));
        int idx = b * HH + hcol;
        float c2 = ff * c_state[idx] + ii * gg;
        c_state[idx] = c2;
        __half hv = __float2half(oo * tanhf(c2));
        int kt = hcol >> 6, r = hcol & 63;
        hT_out[kt * TILE_H + swz_off(r, b >> 3, b & 7)] = hv;
        if (WRITE_LIN) h_lin[idx] = hv;
    }
    consumer_bar();
}

// ---------------- fc phase ----------------
__device__ __forceinline__ void fc_phase(const __half* __restrict__ h1,
                                         const __half* __restrict__ fcw,
                                         const float* __restrict__ fc_b,
                                         float* __restrict__ out,
                                         int t, int tid, int bid) {
    int warp = tid >> 5;
    int gw = bid * 16 + warp;
    int lane = tid & 31;
    for (int task = gw; task < OUTD * BB; task += NCTA * 16) {
        int j = task % OUTD, b = task / OUTD;
        const uint4* w4 = reinterpret_cast<const uint4*>(fcw + (size_t)j * HH);
        const uint4* h4 = reinterpret_cast<const uint4*>(h1 + (size_t)b * HH);
        float s = 0.f;
        #pragma unroll
        for (int it = 0; it < 8; it++) {
            int k = lane + it * 32;
            uint4 wu = w4[k], hu = h4[k];
            const __half2* wp = reinterpret_cast<const __half2*>(&wu);
            const __half2* hp = reinterpret_cast<const __half2*>(&hu);
            #pragma unroll
            for (int e = 0; e < 4; e++) {
                float2 wf = __half22float2(wp[e]);
                float2 hf = __half22float2(hp[e]);
                s += wf.x * hf.x + wf.y * hf.y;
            }
        }
        #pragma unroll
        for (int o = 16; o; o >>= 1) s += __shfl_xor_sync(0xffffffffu, s, o);
        if (lane == 0) {
            float v = s + fc_b[j];
            v = fminf(fmaxf(v, -1.f), 1.f);
            out[(size_t)b * (TT * OUTD) + t * OUTD + j] = v;
            int kt = j >> 6, r = j & 63;
            g_xT[kt * TILE_H + swz_off(r, b >> 3, b & 7)] = __float2half(v);
        }
    }
}

// ---------------- persistent kernel: all 25 steps, ring never drains ----------
__global__ void __launch_bounds__(NTHR, 1)
persist_kernel(const float* __restrict__ fc_b, float* __restrict__ out) {
    extern __shared__ char smc[];
    uint32_t smb = (uint32_t)__cvta_generic_to_shared(smc);
    const int tid = threadIdx.x, bn = blockIdx.x;
    const int lane = tid & 31, warp = tid >> 5;
    const uint32_t fullb  = smb + BAR_OFF;
    const uint32_t emptyb = smb + BAR_OFF + 128;

    if (tid == 0) {
        #pragma unroll
        for (int s = 0; s < NST; s++) {
            mbar_init(fullb + s * 8, 1);
            mbar_init(emptyb + s * 8, 16);
        }
    }
    __syncthreads();

    if (warp == 16) {
        // ------------- producer: 25*49 tiles, continuous stream -------------
        if (lane == 0) {
            const __half* W0 = g_W0p + (size_t)bn * NT0 * TILE_H;
            const __half* W1 = g_W1p + (size_t)bn * NT1 * TILE_H;
            int G = 0;
            auto issue = [&](const __half* act, const __half* wsrc) {
                int s = G % NST;
                if (G >= NST) mbar_wait(emptyb + s * 8, ((G / NST) - 1) & 1);
                mbar_expect_tx(fullb + s * 8, STAGE);
                bulk_g2s(smb + s * STAGE, act, 16384, fullb + s * 8);
                bulk_g2s(smb + s * STAGE + 16384, wsrc, 16384, fullb + s * 8);
                G++;
            };
            for (int t = 0; t < TT; t++) {
                const __half* h0_in = (t & 1) ? g_h0Tb : g_h0Ta;
                const __half* h0_ot = (t & 1) ? g_h0Ta : g_h0Tb;
                const __half* h1_in = (t & 1) ? g_h1Tb : g_h1Ta;
                // cell0 hh tiles (need epi0 of t-1)
                if (t > 0) spin_gpu((unsigned)(3 * t - 2) * NCTA);
                for (int i = 0; i < 16; i++)
                    issue(h0_in + (size_t)i * 8192, W0 + (size_t)i * 8192);
                // cell0 x tile (needs fc of t-1)
                if (t > 0) spin_gpu((unsigned)(3 * t) * NCTA);
                issue(g_xT, W0 + (size_t)16 * 8192);
                // cell1 hh tiles (h1(t-1): covered by fc(t-1) gate above)
                for (int i = 0; i < 16; i++)
                    issue(h1_in + (size_t)i * 8192, W1 + (size_t)i * 8192);
                // cell1 ih tiles (need epi0 of t)
                spin_gpu((unsigned)(3 * t + 1) * NCTA);
                for (int i = 0; i < 16; i++)
                    issue(h0_ot + (size_t)i * 8192, W1 + (size_t)(16 + i) * 8192);
            }
        }
        return;
    }

    // ------------- consumers: 16 warps, 2m x 2n x 4k split -------------
    const int wg = warp & 3, wm2 = (warp >> 2) & 1, wn2 = warp >> 3;
    const int kk = wg * 16;
    const int q = lane >> 3;
    const int kbA = (q >> 1) * 8 + (lane & 7);
    const int arow = (kk + kbA) << 7;
    const int mc0 = wm2 * 32 + (q & 1) * 8;
    const int mc1 = mc0 + 16;
    const int aoff0 = arow + (((((mc0 >> 3) ^ (kbA & 7)) << 3)) << 1);
    const int aoff1 = arow + (((((mc1 >> 3) ^ (kbA & 7)) << 3)) << 1);
    const int jj0 = wn2 * 32 + (lane & 15);
    const int jj1 = jj0 + 16;
    const int klane = lane >> 4;
    const int woff0 = (jj0 << 7) + (((((klane + wg * 2) ^ (jj0 & 7)) << 3)) << 1);
    const int woff1 = (jj1 << 7) + (((((klane + wg * 2) ^ (jj1 & 7)) << 3)) << 1);

    float acc[2][4][4];
    auto zero_acc = [&]() {
        #pragma unroll
        for (int mi = 0; mi < 2; mi++)
            #pragma unroll
            for (int nt = 0; nt < 4; nt++)
                #pragma unroll
                for (int e = 0; e < 4; e++) acc[mi][nt][e] = 0.f;
    };
    auto consume = [&](int t0, int t1) {
        for (int tg = t0; tg < t1; tg++) {
            int s = tg % NST;
            mbar_wait(fullb + s * 8, (tg / NST) & 1);
            uint32_t abase = smb + s * STAGE;
            uint32_t wbase = abase + 16384;
            #pragma unroll
            for (int blk = 0; blk < 2; blk++) {
                uint32_t abuf = abase + blk * 8192;
                uint32_t wbuf = wbase + blk * 8192;
                uint32_t a0[4], a1[4], p[4], qq[4];
                asm volatile("ldmatrix.sync.aligned.m8n8.x4.trans.shared.b16 "
                             "{%0,%1,%2,%3}, [%4];\n"
                             : "=r"(a0[0]), "=r"(a0[1]), "=r"(a0[2]), "=r"(a0[3])
                             : "r"(abuf + aoff0));
                asm volatile("ldmatrix.sync.aligned.m8n8.x4.trans.shared.b16 "
                             "{%0,%1,%2,%3}, [%4];\n"
                             : "=r"(a1[0]), "=r"(a1[1]), "=r"(a1[2]), "=r"(a1[3])
                             : "r"(abuf + aoff1));
                asm volatile("ldmatrix.sync.aligned.m8n8.x4.shared.b16 "
                             "{%0,%1,%2,%3}, [%4];\n"
                             : "=r"(p[0]), "=r"(p[1]), "=r"(p[2]), "=r"(p[3])
                             : "r"(wbuf + woff0));
                asm volatile("ldmatrix.sync.aligned.m8n8.x4.shared.b16 "
                             "{%0,%1,%2,%3}, [%4];\n"
                             : "=r"(qq[0]), "=r"(qq[1]), "=r"(qq[2]), "=r"(qq[3])
                             : "r"(wbuf + woff1));
                #pragma unroll
                for (int mi = 0; mi < 2; mi++) {
                    uint32_t* a = mi ? a1 : a0;
                    mma16816(acc[mi][0], a[0], a[1], a[2], a[3], p[0], p[2]);
                    mma16816(acc[mi][1], a[0], a[1], a[2], a[3], p[1], p[3]);
                    mma16816(acc[mi][2], a[0], a[1], a[2], a[3], qq[0], qq[2]);
                    mma16816(acc[mi][3], a[0], a[1], a[2], a[3], qq[1], qq[3]);
                }
            }
            if (lane == 0) mbar_arrive(emptyb + s * 8);
        }
    };

    for (int t = 0; t < TT; t++) {
        __half* h0_ot = (t & 1) ? g_h0Ta : g_h0Tb;
        __half* h1_ot = (t & 1) ? g_h1Ta : g_h1Tb;
        int base = t * NTT;
        // cell0
        zero_acc();
        consume(base, base + NT0T);
        epilogue<false>(smc, acc, g_bias0, g_c0, h0_ot, nullptr, bn, tid);
        if (tid == 0) { __threadfence(); atomicAdd(&g_barcnt, 1u); }
        // cell1
        zero_acc();
        consume(base + NT0T, base + NTT);
        epilogue<true>(smc, acc, g_bias1, g_c1, h1_ot, g_h1lin, bn, tid);
        if (tid == 0) {
            __threadfence();
            atomicAdd(&g_barcnt, 1u);
            spin_gpu((unsigned)(3 * t + 2) * NCTA);
        }
        consumer_bar();
        fc_phase(g_h1lin, g_fcwh, fc_b, out, t, tid, bn);
        consumer_bar();
        if (tid == 0) { __threadfence(); atomicAdd(&g_barcnt, 1u); }
    }
}

// ---------------- launch ----------------
extern "C" void kernel_launch(void* const* d_in, const int* in_sizes, int n_in,
                              void* d_out, int out_size) {
    (void)in_sizes; (void)n_in; (void)out_size;
    const float* inputs  = (const float*)d_in[0];
    const float* hiddens = (const float*)d_in[1];
    const float* cells   = (const float*)d_in[2];
    const float* W_ih0   = (const float*)d_in[3];
    const float* W_hh0   = (const float*)d_in[4];
    const float* b_ih0   = (const float*)d_in[5];
    const float* b_hh0   = (const float*)d_in[6];
    const float* W_ih1   = (const float*)d_in[7];
    const float* W_hh1   = (const float*)d_in[8];
    const float* b_ih1   = (const float*)d_in[9];
    const float* b_hh1   = (const float*)d_in[10];
    const float* fc_w    = (const float*)d_in[11];
    const float* fc_b    = (const float*)d_in[12];
    float* out = (float*)d_out;

    cudaFuncSetAttribute(persist_kernel,
                         cudaFuncAttributeMaxDynamicSharedMemorySize, SMEM_BYTES);

    const long SETUP_N = 6555136;
    setup_kernel<<<(int)((SETUP_N + 255) / 256), 256>>>(
        inputs, hiddens, cells, W_ih0, W_hh0, b_ih0, b_hh0,
        W_ih1, W_hh1, b_ih1, b_hh1, fc_w);

    persist_kernel<<<NCTA, NTHR, SMEM_BYTES>>>(fc_b, out);
}